// round 1
// baseline (speedup 1.0000x reference)
#include <cuda_runtime.h>
#include <cstdint>

// Problem constants (B=2, S=1024, D=1024, E=8, K=2, H=2048)
#define Ntok 2048
#define Ddim 1024
#define Eexp 8
#define Hdim 2048
#define BSD  (2*1024*1024)
#define ZCOEF 1e-4f

// ---------------- scratch (static device globals: no runtime allocation) ----------------
__device__ float g_zsum;
__device__ float g_psum[Eexp];
__device__ int   g_count[Eexp];
__device__ int   g_list[Eexp * Ntok];
__device__ float g_wlist[Eexp * Ntok];
__device__ float g_act_r[(size_t)Eexp * Ntok * Hdim];  // routed SwiGLU activations (128 MB)
__device__ float g_act_s[(size_t)Ntok * Hdim];         // shared-expert activations (16 MB)

// ---------------- init ----------------
__global__ void init_kernel() {
    int t = threadIdx.x;
    if (t == 0) g_zsum = 0.f;
    if (t < Eexp) { g_psum[t] = 0.f; g_count[t] = 0; }
}

// ---------------- router: logits, top-2, softmax weights, z^2, p_i, expert lists ----------------
__global__ __launch_bounds__(256) void router_kernel(
    const float* __restrict__ x,
    const float* __restrict__ rw,
    const float* __restrict__ rb)
{
    int n = blockIdx.x;
    int t = threadIdx.x;
    int w = t >> 5, lane = t & 31;

    const float* xr = x + (size_t)n * Ddim;
    const float* wr = rw + (size_t)w * Ddim;
    float s = 0.f;
    for (int i = lane; i < Ddim; i += 32) s += xr[i] * wr[i];
    #pragma unroll
    for (int o = 16; o; o >>= 1) s += __shfl_xor_sync(0xFFFFFFFFu, s, o);

    __shared__ float logits[Eexp];
    if (lane == 0) logits[w] = s;
    __syncthreads();

    if (t == 0) {
        float l[Eexp], bsd[Eexp];
        float mx = -1e30f;
        #pragma unroll
        for (int e = 0; e < Eexp; e++) {
            l[e] = logits[e];
            bsd[e] = l[e] + rb[e];       // bias only affects selection (detached)
            mx = fmaxf(mx, l[e]);
        }
        // top-2 on biased logits, ties -> lower index (matches lax.top_k)
        int i0 = 0;
        #pragma unroll
        for (int e = 1; e < Eexp; e++) if (bsd[e] > bsd[i0]) i0 = e;
        int i1 = (i0 == 0) ? 1 : 0;
        #pragma unroll
        for (int e = 0; e < Eexp; e++) if (e != i0 && bsd[e] > bsd[i1]) i1 = e;

        // softmax over the two original logits
        float l0 = l[i0], l1 = l[i1];
        float m2 = fmaxf(l0, l1);
        float e0 = expf(l0 - m2), e1 = expf(l1 - m2);
        float inv = 1.f / (e0 + e1);
        float w0 = e0 * inv, w1 = e1 * inv;

        // logsumexp over all 8 + z^2 accumulation
        float se = 0.f;
        #pragma unroll
        for (int e = 0; e < Eexp; e++) se += expf(l[e] - mx);
        float z = mx + logf(se);
        atomicAdd(&g_zsum, z * z);

        // full softmax probs for p_i
        #pragma unroll
        for (int e = 0; e < Eexp; e++) atomicAdd(&g_psum[e], expf(l[e] - z));

        // build per-expert assignment lists
        int p0 = atomicAdd(&g_count[i0], 1);
        g_list[i0 * Ntok + p0]  = n;
        g_wlist[i0 * Ntok + p0] = w0;
        int p1 = atomicAdd(&g_count[i1], 1);
        g_list[i1 * Ntok + p1]  = n;
        g_wlist[i1 * Ntok + p1] = w1;
    }
}

// ---------------- scalar outputs ----------------
__global__ void finalize_kernel(float* __restrict__ out, int out_size) {
    if (out_size >= BSD + 3) {
        float lb = 0.f;
        #pragma unroll
        for (int e = 0; e < Eexp; e++)
            lb += (g_psum[e] / (float)Ntok) * ((float)g_count[e] / (float)Ntok);
        out[BSD + 0] = 0.f;                              // aux_loss
        out[BSD + 1] = g_zsum / (float)Ntok * ZCOEF;     // router_z_loss
        out[BSD + 2] = lb * (float)Eexp;                 // load_balance
    }
}

// ---------------- GEMM1: act = silu(X @ Wg^T) * (X @ Wu^T)  (fused, gathered rows) ----------------
// Tile 64x64, K-tile 16, 256 threads, 4x4x2 accumulators per thread.
__global__ __launch_bounds__(256) void ffn1_kernel(
    const float* __restrict__ X,
    const float* __restrict__ Wg_base,
    const float* __restrict__ Wu_base,
    float* __restrict__ ACT,
    const int* __restrict__ rowidx_base,
    const int* __restrict__ Mptr, int Mconst)
{
    int e = blockIdx.z;
    const float* Wg = Wg_base + (size_t)e * Hdim * Ddim;
    const float* Wu = Wu_base + (size_t)e * Hdim * Ddim;
    float* act = ACT + (size_t)e * Ntok * Hdim;
    const int* rowidx = rowidx_base ? (rowidx_base + e * Ntok) : nullptr;
    int M = Mptr ? Mptr[e] : Mconst;

    int m0 = blockIdx.y * 64;
    if (m0 >= M) return;
    int n0 = blockIdx.x * 64;

    __shared__ float As[64][17];
    __shared__ float Bg[64][17];
    __shared__ float Bu[64][17];

    int t = threadIdx.x;
    int tx = t & 15, ty = t >> 4;
    int lm = t >> 2, lk = (t & 3) << 2;

    int gm = m0 + lm;
    bool aval = gm < M;
    int arow = aval ? (rowidx ? rowidx[gm] : gm) : 0;
    const float* Arow  = X  + (size_t)arow * Ddim;
    const float* Bgrow = Wg + (size_t)(n0 + lm) * Ddim;
    const float* Burow = Wu + (size_t)(n0 + lm) * Ddim;

    float acc_g[4][4], acc_u[4][4];
    #pragma unroll
    for (int i = 0; i < 4; i++)
        #pragma unroll
        for (int j = 0; j < 4; j++) { acc_g[i][j] = 0.f; acc_u[i][j] = 0.f; }

    for (int k0 = 0; k0 < Ddim; k0 += 16) {
        float4 av = make_float4(0.f, 0.f, 0.f, 0.f);
        if (aval) av = *reinterpret_cast<const float4*>(Arow + k0 + lk);
        float4 gv = *reinterpret_cast<const float4*>(Bgrow + k0 + lk);
        float4 uv = *reinterpret_cast<const float4*>(Burow + k0 + lk);
        As[lm][lk+0] = av.x; As[lm][lk+1] = av.y; As[lm][lk+2] = av.z; As[lm][lk+3] = av.w;
        Bg[lm][lk+0] = gv.x; Bg[lm][lk+1] = gv.y; Bg[lm][lk+2] = gv.z; Bg[lm][lk+3] = gv.w;
        Bu[lm][lk+0] = uv.x; Bu[lm][lk+1] = uv.y; Bu[lm][lk+2] = uv.z; Bu[lm][lk+3] = uv.w;
        __syncthreads();

        #pragma unroll
        for (int kk = 0; kk < 16; kk++) {
            float a[4], bg[4], bu[4];
            #pragma unroll
            for (int i = 0; i < 4; i++) a[i] = As[ty*4 + i][kk];
            #pragma unroll
            for (int j = 0; j < 4; j++) { bg[j] = Bg[tx*4 + j][kk]; bu[j] = Bu[tx*4 + j][kk]; }
            #pragma unroll
            for (int i = 0; i < 4; i++)
                #pragma unroll
                for (int j = 0; j < 4; j++) {
                    acc_g[i][j] += a[i] * bg[j];
                    acc_u[i][j] += a[i] * bu[j];
                }
        }
        __syncthreads();
    }

    #pragma unroll
    for (int i = 0; i < 4; i++) {
        int m = m0 + ty*4 + i;
        if (m >= M) continue;
        #pragma unroll
        for (int j = 0; j < 4; j++) {
            float g = acc_g[i][j], u = acc_u[i][j];
            act[(size_t)m * Hdim + n0 + tx*4 + j] = u * g / (1.f + __expf(-g));
        }
    }
}

// ---------------- GEMM2: Y = act @ Wd^T ; store (shared) or weighted atomic scatter (routed) ----------------
__global__ __launch_bounds__(256) void ffn2_kernel(
    const float* __restrict__ ACT_base,
    const float* __restrict__ Wd_base,
    float* __restrict__ OUT,
    const int* __restrict__ rowidx_base,
    const float* __restrict__ wlist_base,
    const int* __restrict__ Mptr, int Mconst)
{
    int e = blockIdx.z;
    const float* Wd  = Wd_base  + (size_t)e * Ddim * Hdim;
    const float* act = ACT_base + (size_t)e * Ntok * Hdim;
    const int*   rowidx = rowidx_base ? (rowidx_base + e * Ntok) : nullptr;
    const float* wl     = wlist_base  ? (wlist_base  + e * Ntok) : nullptr;
    int M = Mptr ? Mptr[e] : Mconst;

    int m0 = blockIdx.y * 64;
    if (m0 >= M) return;
    int n0 = blockIdx.x * 64;

    __shared__ float As[64][17];
    __shared__ float Bs[64][17];

    int t = threadIdx.x;
    int tx = t & 15, ty = t >> 4;
    int lm = t >> 2, lk = (t & 3) << 2;

    int gm = m0 + lm;
    bool aval = gm < M;
    const float* Arow = act + (size_t)(aval ? gm : 0) * Hdim;
    const float* Brow = Wd  + (size_t)(n0 + lm) * Hdim;

    float acc[4][4];
    #pragma unroll
    for (int i = 0; i < 4; i++)
        #pragma unroll
        for (int j = 0; j < 4; j++) acc[i][j] = 0.f;

    for (int k0 = 0; k0 < Hdim; k0 += 16) {
        float4 av = make_float4(0.f, 0.f, 0.f, 0.f);
        if (aval) av = *reinterpret_cast<const float4*>(Arow + k0 + lk);
        float4 bv = *reinterpret_cast<const float4*>(Brow + k0 + lk);
        As[lm][lk+0] = av.x; As[lm][lk+1] = av.y; As[lm][lk+2] = av.z; As[lm][lk+3] = av.w;
        Bs[lm][lk+0] = bv.x; Bs[lm][lk+1] = bv.y; Bs[lm][lk+2] = bv.z; Bs[lm][lk+3] = bv.w;
        __syncthreads();

        #pragma unroll
        for (int kk = 0; kk < 16; kk++) {
            float a[4], b[4];
            #pragma unroll
            for (int i = 0; i < 4; i++) a[i] = As[ty*4 + i][kk];
            #pragma unroll
            for (int j = 0; j < 4; j++) b[j] = Bs[tx*4 + j][kk];
            #pragma unroll
            for (int i = 0; i < 4; i++)
                #pragma unroll
                for (int j = 0; j < 4; j++) acc[i][j] += a[i] * b[j];
        }
        __syncthreads();
    }

    #pragma unroll
    for (int i = 0; i < 4; i++) {
        int m = m0 + ty*4 + i;
        if (m >= M) continue;
        if (rowidx) {
            int tok = rowidx[m];
            float wt = wl[m];
            #pragma unroll
            for (int j = 0; j < 4; j++)
                atomicAdd(&OUT[(size_t)tok * Ddim + n0 + tx*4 + j], wt * acc[i][j]);
        } else {
            #pragma unroll
            for (int j = 0; j < 4; j++)
                OUT[(size_t)m * Ddim + n0 + tx*4 + j] = acc[i][j];
        }
    }
}

// ---------------- launch ----------------
extern "C" void kernel_launch(void* const* d_in, const int* in_sizes, int n_in,
                              void* d_out, int out_size)
{
    const float* x   = (const float*)d_in[0];
    const float* rw  = (const float*)d_in[1];
    const float* rb  = (const float*)d_in[2];
    const float* gw  = (const float*)d_in[3];
    const float* uw  = (const float*)d_in[4];
    const float* dw  = (const float*)d_in[5];
    const float* shg = (const float*)d_in[6];
    const float* shu = (const float*)d_in[7];
    const float* shd = (const float*)d_in[8];
    float* out = (float*)d_out;

    float *act_r, *act_s, *wlist;
    int *list, *cnt;
    cudaGetSymbolAddress((void**)&act_r, g_act_r);
    cudaGetSymbolAddress((void**)&act_s, g_act_s);
    cudaGetSymbolAddress((void**)&list,  g_list);
    cudaGetSymbolAddress((void**)&wlist, g_wlist);
    cudaGetSymbolAddress((void**)&cnt,   g_count);

    init_kernel<<<1, 32>>>();
    router_kernel<<<Ntok, 256>>>(x, rw, rb);
    finalize_kernel<<<1, 1>>>(out, out_size);

    // shared expert (dense over all tokens)
    ffn1_kernel<<<dim3(Hdim/64, Ntok/64, 1), 256>>>(x, shg, shu, act_s, nullptr, nullptr, Ntok);
    // routed experts (gathered rows, per-expert counts read on device)
    ffn1_kernel<<<dim3(Hdim/64, Ntok/64, Eexp), 256>>>(x, gw, uw, act_r, list, cnt, 0);

    // shared down-proj: plain store (covers every output element) ...
    ffn2_kernel<<<dim3(Ddim/64, Ntok/64, 1), 256>>>(act_s, shd, out, nullptr, nullptr, nullptr, Ntok);
    // ... then routed down-proj: weighted atomic accumulation on top
    ffn2_kernel<<<dim3(Ddim/64, Ntok/64, Eexp), 256>>>(act_r, dw, out, list, wlist, cnt, 0);
}

// round 3
// speedup vs baseline: 3.1888x; 3.1888x over previous
#include <cuda_runtime.h>
#include <cstdint>

// Problem constants (B=2, S=1024, D=1024, E=8, K=2, H=2048)
#define Ntok 2048
#define Ddim 1024
#define Eexp 8
#define Hdim 2048
#define BSD  (2*1024*1024)
#define ZCOEF 1e-4f

// ---------------- scratch (static device globals) ----------------
__device__ float g_zsum;
__device__ float g_psum[Eexp];
__device__ int   g_count[Eexp];
__device__ int   g_list[Eexp * Ntok];
__device__ float g_wlist[Eexp * Ntok];
__device__ float g_act_r[(size_t)Eexp * Ntok * Hdim];  // routed SwiGLU activations (wt pre-folded)
__device__ float g_act_s[(size_t)Ntok * Hdim];         // shared-expert activations

// ---------------- helpers ----------------
// round-to-nearest fp32 -> tf32 (kept in 32-bit container)
__device__ __forceinline__ float rtf(float x) {
    uint32_t r;
    asm("cvt.rna.tf32.f32 %0, %1;" : "=r"(r) : "f"(x));
    return __uint_as_float(r);
}
__device__ __forceinline__ void mma_tf32(float c[4],
    uint32_t a0, uint32_t a1, uint32_t a2, uint32_t a3,
    uint32_t b0, uint32_t b1)
{
    asm volatile(
        "mma.sync.aligned.m16n8k8.row.col.f32.tf32.tf32.f32 "
        "{%0,%1,%2,%3}, {%4,%5,%6,%7}, {%8,%9}, {%0,%1,%2,%3};"
        : "+f"(c[0]), "+f"(c[1]), "+f"(c[2]), "+f"(c[3])
        : "r"(a0), "r"(a1), "r"(a2), "r"(a3), "r"(b0), "r"(b1));
}
__device__ __forceinline__ float silu(float x) { return x / (1.f + __expf(-x)); }
__device__ __forceinline__ void st4(float* p, float4 v) {
    float4 t; t.x = rtf(v.x); t.y = rtf(v.y); t.z = rtf(v.z); t.w = rtf(v.w);
    *reinterpret_cast<float4*>(p) = t;
}

// ---------------- init ----------------
__global__ void init_kernel() {
    int t = threadIdx.x;
    if (t == 0) g_zsum = 0.f;
    if (t < Eexp) { g_psum[t] = 0.f; g_count[t] = 0; }
}

// ---------------- router ----------------
__global__ __launch_bounds__(256) void router_kernel(
    const float* __restrict__ x,
    const float* __restrict__ rw,
    const float* __restrict__ rb)
{
    int n = blockIdx.x;
    int t = threadIdx.x;
    int w = t >> 5, lane = t & 31;

    const float* xr = x + (size_t)n * Ddim;
    const float* wr = rw + (size_t)w * Ddim;
    float s = 0.f;
    for (int i = lane; i < Ddim; i += 32) s += xr[i] * wr[i];
    #pragma unroll
    for (int o = 16; o; o >>= 1) s += __shfl_xor_sync(0xFFFFFFFFu, s, o);

    __shared__ float logits[Eexp];
    if (lane == 0) logits[w] = s;
    __syncthreads();

    if (t == 0) {
        float l[Eexp], bsd[Eexp];
        float mx = -1e30f;
        #pragma unroll
        for (int e = 0; e < Eexp; e++) {
            l[e] = logits[e];
            bsd[e] = l[e] + rb[e];
            mx = fmaxf(mx, l[e]);
        }
        int i0 = 0;
        #pragma unroll
        for (int e = 1; e < Eexp; e++) if (bsd[e] > bsd[i0]) i0 = e;
        int i1 = (i0 == 0) ? 1 : 0;
        #pragma unroll
        for (int e = 0; e < Eexp; e++) if (e != i0 && bsd[e] > bsd[i1]) i1 = e;

        float l0 = l[i0], l1 = l[i1];
        float m2 = fmaxf(l0, l1);
        float e0 = expf(l0 - m2), e1 = expf(l1 - m2);
        float inv = 1.f / (e0 + e1);
        float w0 = e0 * inv, w1 = e1 * inv;

        float se = 0.f;
        #pragma unroll
        for (int e = 0; e < Eexp; e++) se += expf(l[e] - mx);
        float z = mx + logf(se);
        atomicAdd(&g_zsum, z * z);

        #pragma unroll
        for (int e = 0; e < Eexp; e++) atomicAdd(&g_psum[e], expf(l[e] - z));

        int p0 = atomicAdd(&g_count[i0], 1);
        g_list[i0 * Ntok + p0]  = n;
        g_wlist[i0 * Ntok + p0] = w0;
        int p1 = atomicAdd(&g_count[i1], 1);
        g_list[i1 * Ntok + p1]  = n;
        g_wlist[i1 * Ntok + p1] = w1;
    }
}

// ---------------- scalar outputs ----------------
__global__ void finalize_kernel(float* __restrict__ out, int out_size) {
    if (out_size >= BSD + 3) {
        float lb = 0.f;
        #pragma unroll
        for (int e = 0; e < Eexp; e++)
            lb += (g_psum[e] / (float)Ntok) * ((float)g_count[e] / (float)Ntok);
        out[BSD + 0] = 0.f;
        out[BSD + 1] = g_zsum / (float)Ntok * ZCOEF;
        out[BSD + 2] = lb * (float)Eexp;
    }
}

// =====================================================================
// ffn1_mma: act[m, n0..n0+63] = wt * silu(X@Wg^T) * (X@Wu^T)
// CTA tile 128(m) x 64(n), K-tile 32. 8 warps (4m x 2n), warp 32x32.
// SMEM rows stride 36 floats: all fragment LDS.32 conflict-free.
// =====================================================================
#define STG1 9216   // floats per stage: A 128*36=4608, Bg 64*36=2304, Bu 2304
__global__ __launch_bounds__(256) void ffn1_mma(
    const float* __restrict__ X,
    const float* __restrict__ Wg_base,
    const float* __restrict__ Wu_base,
    float* __restrict__ ACT,
    const int* __restrict__ rowidx_base,
    const float* __restrict__ wlist_base,
    const int* __restrict__ Mptr, int Mconst)
{
    int e = blockIdx.z;
    int M = Mptr ? Mptr[e] : Mconst;
    int m0 = blockIdx.y * 128;
    if (m0 >= M) return;
    int n0 = blockIdx.x * 64;

    const float* Wg = Wg_base + (size_t)e * Hdim * Ddim;
    const float* Wu = Wu_base + (size_t)e * Hdim * Ddim;
    float* act = ACT + (size_t)e * Ntok * Hdim;
    const int* rowidx = rowidx_base ? rowidx_base + e * Ntok : nullptr;
    const float* wl   = wlist_base  ? wlist_base  + e * Ntok : nullptr;

    extern __shared__ float sm[];

    int tid = threadIdx.x, lane = tid & 31, wid = tid >> 5;
    int g = lane >> 2, tig = lane & 3;
    int wm = wid & 3, wn = wid >> 2;
    int mw = wm * 32, nw = wn * 32;

    // loader mapping
    int lr = tid >> 3, lc = tid & 7;
    const float* aptr[4];
    #pragma unroll
    for (int i = 0; i < 4; i++) {
        int mm = m0 + lr + 32 * i;
        int src = mm < M ? mm : (M - 1);
        int row = rowidx ? rowidx[src] : src;
        aptr[i] = X + (size_t)row * Ddim + lc * 4;
    }
    const float *gptr[2], *uptr[2];
    #pragma unroll
    for (int i = 0; i < 2; i++) {
        int r = n0 + lr + 32 * i;
        gptr[i] = Wg + (size_t)r * Ddim + lc * 4;
        uptr[i] = Wu + (size_t)r * Ddim + lc * 4;
    }
    int sA[4], sB[2];
    #pragma unroll
    for (int i = 0; i < 4; i++) sA[i] = (lr + 32 * i) * 36 + lc * 4;
    #pragma unroll
    for (int i = 0; i < 2; i++) sB[i] = (lr + 32 * i) * 36 + lc * 4;

    float accg[2][4][4], accu[2][4][4];
    #pragma unroll
    for (int a = 0; a < 2; a++)
        #pragma unroll
        for (int b = 0; b < 4; b++)
            #pragma unroll
            for (int c = 0; c < 4; c++) { accg[a][b][c] = 0.f; accu[a][b][c] = 0.f; }

    float4 pa[4], pg[2], pu[2];
    #pragma unroll
    for (int i = 0; i < 4; i++) pa[i] = *reinterpret_cast<const float4*>(aptr[i]);
    #pragma unroll
    for (int i = 0; i < 2; i++) { pg[i] = *reinterpret_cast<const float4*>(gptr[i]);
                                  pu[i] = *reinterpret_cast<const float4*>(uptr[i]); }
    {
        float* D = sm;
        #pragma unroll
        for (int i = 0; i < 4; i++) st4(D + sA[i], pa[i]);
        #pragma unroll
        for (int i = 0; i < 2; i++) { st4(D + 4608 + sB[i], pg[i]); st4(D + 6912 + sB[i], pu[i]); }
    }
    __syncthreads();

    const int NT = Ddim / 32;
    for (int kt = 0; kt < NT; kt++) {
        int cur = kt & 1;
        if (kt + 1 < NT) {
            int off = (kt + 1) * 32;
            #pragma unroll
            for (int i = 0; i < 4; i++) pa[i] = *reinterpret_cast<const float4*>(aptr[i] + off);
            #pragma unroll
            for (int i = 0; i < 2; i++) { pg[i] = *reinterpret_cast<const float4*>(gptr[i] + off);
                                          pu[i] = *reinterpret_cast<const float4*>(uptr[i] + off); }
        }
        const uint32_t* A = reinterpret_cast<const uint32_t*>(sm + cur * STG1);
        const uint32_t* G = A + 4608;
        const uint32_t* U = A + 6912;
        #pragma unroll
        for (int s = 0; s < 4; s++) {
            int k8 = s * 8;
            uint32_t af[2][4];
            #pragma unroll
            for (int mf = 0; mf < 2; mf++) {
                int rb = (mw + mf * 16 + g) * 36 + k8 + tig;
                af[mf][0] = A[rb];           af[mf][1] = A[rb + 8 * 36];
                af[mf][2] = A[rb + 4];       af[mf][3] = A[rb + 8 * 36 + 4];
            }
            uint32_t bg[4][2], bu[4][2];
            #pragma unroll
            for (int nf = 0; nf < 4; nf++) {
                int rb = (nw + nf * 8 + g) * 36 + k8 + tig;
                bg[nf][0] = G[rb]; bg[nf][1] = G[rb + 4];
                bu[nf][0] = U[rb]; bu[nf][1] = U[rb + 4];
            }
            #pragma unroll
            for (int mf = 0; mf < 2; mf++)
                #pragma unroll
                for (int nf = 0; nf < 4; nf++) {
                    mma_tf32(accg[mf][nf], af[mf][0], af[mf][1], af[mf][2], af[mf][3], bg[nf][0], bg[nf][1]);
                    mma_tf32(accu[mf][nf], af[mf][0], af[mf][1], af[mf][2], af[mf][3], bu[nf][0], bu[nf][1]);
                }
        }
        if (kt + 1 < NT) {
            float* D = sm + (cur ^ 1) * STG1;
            #pragma unroll
            for (int i = 0; i < 4; i++) st4(D + sA[i], pa[i]);
            #pragma unroll
            for (int i = 0; i < 2; i++) { st4(D + 4608 + sB[i], pg[i]); st4(D + 6912 + sB[i], pu[i]); }
        }
        __syncthreads();
    }

    // epilogue: act row m gets wt * silu(g) * u
    #pragma unroll
    for (int mf = 0; mf < 2; mf++) {
        int m1 = m0 + mw + mf * 16 + g;
        int m2 = m1 + 8;
        float wt1 = (m1 < M) ? (wl ? wl[m1] : 1.f) : 0.f;
        float wt2 = (m2 < M) ? (wl ? wl[m2] : 1.f) : 0.f;
        #pragma unroll
        for (int nf = 0; nf < 4; nf++) {
            int n = n0 + nw + nf * 8 + 2 * tig;
            if (m1 < M) {
                float2 o;
                o.x = wt1 * silu(accg[mf][nf][0]) * accu[mf][nf][0];
                o.y = wt1 * silu(accg[mf][nf][1]) * accu[mf][nf][1];
                *reinterpret_cast<float2*>(act + (size_t)m1 * Hdim + n) = o;
            }
            if (m2 < M) {
                float2 o;
                o.x = wt2 * silu(accg[mf][nf][2]) * accu[mf][nf][2];
                o.y = wt2 * silu(accg[mf][nf][3]) * accu[mf][nf][3];
                *reinterpret_cast<float2*>(act + (size_t)m2 * Hdim + n) = o;
            }
        }
    }
}

// =====================================================================
// ffn2_mma: Y = ACT @ Wd^T ; shared: plain store; routed: atomicAdd
// CTA tile 128x128, K-tile 32. 8 warps (2m x 4n), warp 64x32.
// =====================================================================
#define STG2 9216   // floats per stage: A 128*36=4608, B 128*36=4608
__global__ __launch_bounds__(256) void ffn2_mma(
    const float* __restrict__ ACT_base,
    const float* __restrict__ Wd_base,
    float* __restrict__ OUT,
    const int* __restrict__ rowidx_base,
    const int* __restrict__ Mptr, int Mconst)
{
    int e = blockIdx.z;
    int M = Mptr ? Mptr[e] : Mconst;
    int m0 = blockIdx.y * 128;
    if (m0 >= M) return;
    int n0 = blockIdx.x * 128;

    const float* Wd  = Wd_base  + (size_t)e * Ddim * Hdim;
    const float* act = ACT_base + (size_t)e * Ntok * Hdim;
    const int* rowidx = rowidx_base ? rowidx_base + e * Ntok : nullptr;

    extern __shared__ float sm[];

    int tid = threadIdx.x, lane = tid & 31, wid = tid >> 5;
    int g = lane >> 2, tig = lane & 3;
    int wm = wid >> 2, wn = wid & 3;
    int mw = wm * 64, nw = wn * 32;

    int lr = tid >> 3, lc = tid & 7;
    const float* aptr[4];
    const float* bptr[4];
    #pragma unroll
    for (int i = 0; i < 4; i++) {
        int mm = m0 + lr + 32 * i;
        int src = mm < M ? mm : (M - 1);
        aptr[i] = act + (size_t)src * Hdim + lc * 4;      // ACT rows dense in list order
        bptr[i] = Wd  + (size_t)(n0 + lr + 32 * i) * Hdim + lc * 4;
    }
    int sO[4];
    #pragma unroll
    for (int i = 0; i < 4; i++) sO[i] = (lr + 32 * i) * 36 + lc * 4;

    float acc[4][4][4];
    #pragma unroll
    for (int a = 0; a < 4; a++)
        #pragma unroll
        for (int b = 0; b < 4; b++)
            #pragma unroll
            for (int c = 0; c < 4; c++) acc[a][b][c] = 0.f;

    float4 pa[4], pb[4];
    #pragma unroll
    for (int i = 0; i < 4; i++) { pa[i] = *reinterpret_cast<const float4*>(aptr[i]);
                                  pb[i] = *reinterpret_cast<const float4*>(bptr[i]); }
    {
        float* D = sm;
        #pragma unroll
        for (int i = 0; i < 4; i++) { st4(D + sO[i], pa[i]); st4(D + 4608 + sO[i], pb[i]); }
    }
    __syncthreads();

    const int NT = Hdim / 32;
    for (int kt = 0; kt < NT; kt++) {
        int cur = kt & 1;
        if (kt + 1 < NT) {
            int off = (kt + 1) * 32;
            #pragma unroll
            for (int i = 0; i < 4; i++) { pa[i] = *reinterpret_cast<const float4*>(aptr[i] + off);
                                          pb[i] = *reinterpret_cast<const float4*>(bptr[i] + off); }
        }
        const uint32_t* A = reinterpret_cast<const uint32_t*>(sm + cur * STG2);
        const uint32_t* B = A + 4608;
        #pragma unroll
        for (int s = 0; s < 4; s++) {
            int k8 = s * 8;
            uint32_t af[4][4];
            #pragma unroll
            for (int mf = 0; mf < 4; mf++) {
                int rb = (mw + mf * 16 + g) * 36 + k8 + tig;
                af[mf][0] = A[rb];           af[mf][1] = A[rb + 8 * 36];
                af[mf][2] = A[rb + 4];       af[mf][3] = A[rb + 8 * 36 + 4];
            }
            uint32_t bf[4][2];
            #pragma unroll
            for (int nf = 0; nf < 4; nf++) {
                int rb = (nw + nf * 8 + g) * 36 + k8 + tig;
                bf[nf][0] = B[rb]; bf[nf][1] = B[rb + 4];
            }
            #pragma unroll
            for (int mf = 0; mf < 4; mf++)
                #pragma unroll
                for (int nf = 0; nf < 4; nf++)
                    mma_tf32(acc[mf][nf], af[mf][0], af[mf][1], af[mf][2], af[mf][3], bf[nf][0], bf[nf][1]);
        }
        if (kt + 1 < NT) {
            float* D = sm + (cur ^ 1) * STG2;
            #pragma unroll
            for (int i = 0; i < 4; i++) { st4(D + sO[i], pa[i]); st4(D + 4608 + sO[i], pb[i]); }
        }
        __syncthreads();
    }

    // epilogue
    #pragma unroll
    for (int mf = 0; mf < 4; mf++) {
        int m1 = m0 + mw + mf * 16 + g;
        int m2 = m1 + 8;
        #pragma unroll
        for (int nf = 0; nf < 4; nf++) {
            int n = n0 + nw + nf * 8 + 2 * tig;
            if (rowidx) {
                if (m1 < M) {
                    float* p = OUT + (size_t)rowidx[m1] * Ddim + n;
                    atomicAdd(p,     acc[mf][nf][0]);
                    atomicAdd(p + 1, acc[mf][nf][1]);
                }
                if (m2 < M) {
                    float* p = OUT + (size_t)rowidx[m2] * Ddim + n;
                    atomicAdd(p,     acc[mf][nf][2]);
                    atomicAdd(p + 1, acc[mf][nf][3]);
                }
            } else {
                if (m1 < M) {
                    float2 o; o.x = acc[mf][nf][0]; o.y = acc[mf][nf][1];
                    *reinterpret_cast<float2*>(OUT + (size_t)m1 * Ddim + n) = o;
                }
                if (m2 < M) {
                    float2 o; o.x = acc[mf][nf][2]; o.y = acc[mf][nf][3];
                    *reinterpret_cast<float2*>(OUT + (size_t)m2 * Ddim + n) = o;
                }
            }
        }
    }
}

// ---------------- launch ----------------
#define FFN1_SMEM (2 * STG1 * 4)
#define FFN2_SMEM (2 * STG2 * 4)

extern "C" void kernel_launch(void* const* d_in, const int* in_sizes, int n_in,
                              void* d_out, int out_size)
{
    const float* x   = (const float*)d_in[0];
    const float* rw  = (const float*)d_in[1];
    const float* rb  = (const float*)d_in[2];
    const float* gw  = (const float*)d_in[3];
    const float* uw  = (const float*)d_in[4];
    const float* dw  = (const float*)d_in[5];
    const float* shg = (const float*)d_in[6];
    const float* shu = (const float*)d_in[7];
    const float* shd = (const float*)d_in[8];
    float* out = (float*)d_out;

    float *act_r, *act_s, *wlist;
    int *list, *cnt;
    cudaGetSymbolAddress((void**)&act_r, g_act_r);
    cudaGetSymbolAddress((void**)&act_s, g_act_s);
    cudaGetSymbolAddress((void**)&list,  g_list);
    cudaGetSymbolAddress((void**)&wlist, g_wlist);
    cudaGetSymbolAddress((void**)&cnt,   g_count);

    cudaFuncSetAttribute(ffn1_mma, cudaFuncAttributeMaxDynamicSharedMemorySize, FFN1_SMEM);
    cudaFuncSetAttribute(ffn2_mma, cudaFuncAttributeMaxDynamicSharedMemorySize, FFN2_SMEM);

    init_kernel<<<1, 32>>>();
    router_kernel<<<Ntok, 256>>>(x, rw, rb);
    finalize_kernel<<<1, 1>>>(out, out_size);

    // gate/up + SwiGLU (+wt folded for routed)
    ffn1_mma<<<dim3(Hdim/64, Ntok/128, 1),    256, FFN1_SMEM>>>(x, shg, shu, act_s, nullptr, nullptr, nullptr, Ntok);
    ffn1_mma<<<dim3(Hdim/64, Ntok/128, Eexp), 256, FFN1_SMEM>>>(x, gw, uw, act_r, list, wlist, cnt, 0);

    // down-proj: shared writes every element, routed accumulates on top
    ffn2_mma<<<dim3(Ddim/128, Ntok/128, 1),    256, FFN2_SMEM>>>(act_s, shd, out, nullptr, nullptr, Ntok);
    ffn2_mma<<<dim3(Ddim/128, Ntok/128, Eexp), 256, FFN2_SMEM>>>(act_r, dw, out, list, cnt, 0);
}

// round 4
// speedup vs baseline: 3.7161x; 1.1654x over previous
#include <cuda_runtime.h>
#include <cstdint>

// Problem constants (B=2, S=1024, D=1024, E=8, K=2, H=2048)
#define Ntok 2048
#define Ddim 1024
#define Eexp 8
#define Hdim 2048
#define BSD  (2*1024*1024)
#define ZCOEF 1e-4f

// ---------------- scratch (static device globals) ----------------
__device__ float g_zsum;
__device__ float g_psum[Eexp];
__device__ int   g_count[Eexp];
__device__ int   g_list[Eexp * Ntok];
__device__ float g_wlist[Eexp * Ntok];
__device__ float g_act_r[(size_t)Eexp * Ntok * Hdim];  // routed SwiGLU activations (wt pre-folded)
__device__ float g_act_s[(size_t)Ntok * Hdim];         // shared-expert activations

// ---------------- helpers ----------------
__device__ __forceinline__ float rtf(float x) {
    uint32_t r;
    asm("cvt.rna.tf32.f32 %0, %1;" : "=r"(r) : "f"(x));
    return __uint_as_float(r);
}
__device__ __forceinline__ void mma_tf32(float c[4],
    uint32_t a0, uint32_t a1, uint32_t a2, uint32_t a3,
    uint32_t b0, uint32_t b1)
{
    asm volatile(
        "mma.sync.aligned.m16n8k8.row.col.f32.tf32.tf32.f32 "
        "{%0,%1,%2,%3}, {%4,%5,%6,%7}, {%8,%9}, {%0,%1,%2,%3};"
        : "+f"(c[0]), "+f"(c[1]), "+f"(c[2]), "+f"(c[3])
        : "r"(a0), "r"(a1), "r"(a2), "r"(a3), "r"(b0), "r"(b1));
}
__device__ __forceinline__ float silu(float x) { return x / (1.f + __expf(-x)); }
__device__ __forceinline__ void st4(float* p, float4 v) {
    float4 t; t.x = rtf(v.x); t.y = rtf(v.y); t.z = rtf(v.z); t.w = rtf(v.w);
    *reinterpret_cast<float4*>(p) = t;
}

// ---------------- init ----------------
__global__ void init_kernel() {
    int t = threadIdx.x;
    if (t == 0) g_zsum = 0.f;
    if (t < Eexp) { g_psum[t] = 0.f; g_count[t] = 0; }
}

// ---------------- router ----------------
__global__ __launch_bounds__(256) void router_kernel(
    const float* __restrict__ x,
    const float* __restrict__ rw,
    const float* __restrict__ rb)
{
    int n = blockIdx.x;
    int t = threadIdx.x;
    int w = t >> 5, lane = t & 31;

    const float* xr = x + (size_t)n * Ddim;
    const float* wr = rw + (size_t)w * Ddim;
    float s = 0.f;
    for (int i = lane; i < Ddim; i += 32) s += xr[i] * wr[i];
    #pragma unroll
    for (int o = 16; o; o >>= 1) s += __shfl_xor_sync(0xFFFFFFFFu, s, o);

    __shared__ float logits[Eexp];
    if (lane == 0) logits[w] = s;
    __syncthreads();

    if (t == 0) {
        float l[Eexp], bsd[Eexp];
        float mx = -1e30f;
        #pragma unroll
        for (int e = 0; e < Eexp; e++) {
            l[e] = logits[e];
            bsd[e] = l[e] + rb[e];
            mx = fmaxf(mx, l[e]);
        }
        int i0 = 0;
        #pragma unroll
        for (int e = 1; e < Eexp; e++) if (bsd[e] > bsd[i0]) i0 = e;
        int i1 = (i0 == 0) ? 1 : 0;
        #pragma unroll
        for (int e = 0; e < Eexp; e++) if (e != i0 && bsd[e] > bsd[i1]) i1 = e;

        float l0 = l[i0], l1 = l[i1];
        float m2 = fmaxf(l0, l1);
        float e0 = expf(l0 - m2), e1 = expf(l1 - m2);
        float inv = 1.f / (e0 + e1);
        float w0 = e0 * inv, w1 = e1 * inv;

        float se = 0.f;
        #pragma unroll
        for (int e = 0; e < Eexp; e++) se += expf(l[e] - mx);
        float z = mx + logf(se);
        atomicAdd(&g_zsum, z * z);

        #pragma unroll
        for (int e = 0; e < Eexp; e++) atomicAdd(&g_psum[e], expf(l[e] - z));

        int p0 = atomicAdd(&g_count[i0], 1);
        g_list[i0 * Ntok + p0]  = n;
        g_wlist[i0 * Ntok + p0] = w0;
        int p1 = atomicAdd(&g_count[i1], 1);
        g_list[i1 * Ntok + p1]  = n;
        g_wlist[i1 * Ntok + p1] = w1;
    }
}

// ---------------- scalar outputs ----------------
__global__ void finalize_kernel(float* __restrict__ out, int out_size) {
    if (out_size >= BSD + 3) {
        float lb = 0.f;
        #pragma unroll
        for (int e = 0; e < Eexp; e++)
            lb += (g_psum[e] / (float)Ntok) * ((float)g_count[e] / (float)Ntok);
        out[BSD + 0] = 0.f;
        out[BSD + 1] = g_zsum / (float)Ntok * ZCOEF;
        out[BSD + 2] = lb * (float)Eexp;
    }
}

// =====================================================================
// ffn1_mma: act[m, n0..n0+63] = wt * silu(X@Wg^T) * (X@Wu^T)
// CTA tile 128(m) x 64(n), K-tile 32. 8 warps (4m x 2n), warp 32x32(x2).
// SMEM rows stride 36 floats: fragment LDS.32 conflict-free.
// __launch_bounds__(256,2): cap 128 regs so 2 CTAs/SM (occupancy 2x).
// =====================================================================
#define STG1 9216   // floats per stage: A 128*36=4608, Bg 64*36=2304, Bu 2304
__global__ __launch_bounds__(256, 2) void ffn1_mma(
    const float* __restrict__ X,
    const float* __restrict__ Wg_base,
    const float* __restrict__ Wu_base,
    float* __restrict__ ACT,
    const int* __restrict__ rowidx_base,
    const float* __restrict__ wlist_base,
    const int* __restrict__ Mptr, int Mconst)
{
    int e = blockIdx.z;
    int M = Mptr ? Mptr[e] : Mconst;
    int m0 = blockIdx.y * 128;
    if (m0 >= M) return;
    int n0 = blockIdx.x * 64;

    const float* Wg = Wg_base + (size_t)e * Hdim * Ddim;
    const float* Wu = Wu_base + (size_t)e * Hdim * Ddim;
    float* act = ACT + (size_t)e * Ntok * Hdim;
    const int* rowidx = rowidx_base ? rowidx_base + e * Ntok : nullptr;
    const float* wl   = wlist_base  ? wlist_base  + e * Ntok : nullptr;

    extern __shared__ float sm[];

    int tid = threadIdx.x, lane = tid & 31, wid = tid >> 5;
    int g = lane >> 2, tig = lane & 3;
    int wm = wid & 3, wn = wid >> 2;
    int mw = wm * 32, nw = wn * 32;

    // loader mapping
    int lr = tid >> 3, lc = tid & 7;
    const float* aptr[4];
    #pragma unroll
    for (int i = 0; i < 4; i++) {
        int mm = m0 + lr + 32 * i;
        int src = mm < M ? mm : (M - 1);
        int row = rowidx ? rowidx[src] : src;
        aptr[i] = X + (size_t)row * Ddim + lc * 4;
    }
    const float *gptr[2], *uptr[2];
    #pragma unroll
    for (int i = 0; i < 2; i++) {
        int r = n0 + lr + 32 * i;
        gptr[i] = Wg + (size_t)r * Ddim + lc * 4;
        uptr[i] = Wu + (size_t)r * Ddim + lc * 4;
    }
    int sA[4], sB[2];
    #pragma unroll
    for (int i = 0; i < 4; i++) sA[i] = (lr + 32 * i) * 36 + lc * 4;
    #pragma unroll
    for (int i = 0; i < 2; i++) sB[i] = (lr + 32 * i) * 36 + lc * 4;

    // fragment SMEM bases (hoisted out of mainloop; ALU reduction)
    int aBase[2], bBase[4];
    #pragma unroll
    for (int mf = 0; mf < 2; mf++) aBase[mf] = (mw + mf * 16 + g) * 36 + tig;
    #pragma unroll
    for (int nf = 0; nf < 4; nf++) bBase[nf] = (nw + nf * 8 + g) * 36 + tig;

    float accg[2][4][4], accu[2][4][4];
    #pragma unroll
    for (int a = 0; a < 2; a++)
        #pragma unroll
        for (int b = 0; b < 4; b++)
            #pragma unroll
            for (int c = 0; c < 4; c++) { accg[a][b][c] = 0.f; accu[a][b][c] = 0.f; }

    float4 pa[4], pg[2], pu[2];
    #pragma unroll
    for (int i = 0; i < 4; i++) pa[i] = *reinterpret_cast<const float4*>(aptr[i]);
    #pragma unroll
    for (int i = 0; i < 2; i++) { pg[i] = *reinterpret_cast<const float4*>(gptr[i]);
                                  pu[i] = *reinterpret_cast<const float4*>(uptr[i]); }
    {
        float* D = sm;
        #pragma unroll
        for (int i = 0; i < 4; i++) st4(D + sA[i], pa[i]);
        #pragma unroll
        for (int i = 0; i < 2; i++) { st4(D + 4608 + sB[i], pg[i]); st4(D + 6912 + sB[i], pu[i]); }
    }
    __syncthreads();

    const int NT = Ddim / 32;
    for (int kt = 0; kt < NT; kt++) {
        int cur = kt & 1;
        if (kt + 1 < NT) {
            int off = (kt + 1) * 32;
            #pragma unroll
            for (int i = 0; i < 4; i++) pa[i] = *reinterpret_cast<const float4*>(aptr[i] + off);
            #pragma unroll
            for (int i = 0; i < 2; i++) { pg[i] = *reinterpret_cast<const float4*>(gptr[i] + off);
                                          pu[i] = *reinterpret_cast<const float4*>(uptr[i] + off); }
        }
        const uint32_t* A = reinterpret_cast<const uint32_t*>(sm + cur * STG1);
        const uint32_t* G = A + 4608;
        const uint32_t* U = A + 6912;
        #pragma unroll
        for (int s = 0; s < 4; s++) {
            int k8 = s * 8;
            uint32_t af[2][4];
            #pragma unroll
            for (int mf = 0; mf < 2; mf++) {
                int rb = aBase[mf] + k8;
                af[mf][0] = A[rb];           af[mf][1] = A[rb + 8 * 36];
                af[mf][2] = A[rb + 4];       af[mf][3] = A[rb + 8 * 36 + 4];
            }
            uint32_t bg[4][2], bu[4][2];
            #pragma unroll
            for (int nf = 0; nf < 4; nf++) {
                int rb = bBase[nf] + k8;
                bg[nf][0] = G[rb]; bg[nf][1] = G[rb + 4];
                bu[nf][0] = U[rb]; bu[nf][1] = U[rb + 4];
            }
            #pragma unroll
            for (int mf = 0; mf < 2; mf++)
                #pragma unroll
                for (int nf = 0; nf < 4; nf++) {
                    mma_tf32(accg[mf][nf], af[mf][0], af[mf][1], af[mf][2], af[mf][3], bg[nf][0], bg[nf][1]);
                    mma_tf32(accu[mf][nf], af[mf][0], af[mf][1], af[mf][2], af[mf][3], bu[nf][0], bu[nf][1]);
                }
        }
        if (kt + 1 < NT) {
            float* D = sm + (cur ^ 1) * STG1;
            #pragma unroll
            for (int i = 0; i < 4; i++) st4(D + sA[i], pa[i]);
            #pragma unroll
            for (int i = 0; i < 2; i++) { st4(D + 4608 + sB[i], pg[i]); st4(D + 6912 + sB[i], pu[i]); }
        }
        __syncthreads();
    }

    // epilogue: act row m gets wt * silu(g) * u
    #pragma unroll
    for (int mf = 0; mf < 2; mf++) {
        int m1 = m0 + mw + mf * 16 + g;
        int m2 = m1 + 8;
        float wt1 = (m1 < M) ? (wl ? wl[m1] : 1.f) : 0.f;
        float wt2 = (m2 < M) ? (wl ? wl[m2] : 1.f) : 0.f;
        #pragma unroll
        for (int nf = 0; nf < 4; nf++) {
            int n = n0 + nw + nf * 8 + 2 * tig;
            if (m1 < M) {
                float2 o;
                o.x = wt1 * silu(accg[mf][nf][0]) * accu[mf][nf][0];
                o.y = wt1 * silu(accg[mf][nf][1]) * accu[mf][nf][1];
                *reinterpret_cast<float2*>(act + (size_t)m1 * Hdim + n) = o;
            }
            if (m2 < M) {
                float2 o;
                o.x = wt2 * silu(accg[mf][nf][2]) * accu[mf][nf][2];
                o.y = wt2 * silu(accg[mf][nf][3]) * accu[mf][nf][3];
                *reinterpret_cast<float2*>(act + (size_t)m2 * Hdim + n) = o;
            }
        }
    }
}

// =====================================================================
// ffn2_mma: Y = ACT @ Wd^T ; shared: plain store; routed: atomicAdd
// CTA tile 128x128, K-tile 32. 8 warps (2m x 4n), warp 64x32.
// =====================================================================
#define STG2 9216   // floats per stage: A 128*36=4608, B 128*36=4608
__global__ __launch_bounds__(256, 2) void ffn2_mma(
    const float* __restrict__ ACT_base,
    const float* __restrict__ Wd_base,
    float* __restrict__ OUT,
    const int* __restrict__ rowidx_base,
    const int* __restrict__ Mptr, int Mconst)
{
    int e = blockIdx.z;
    int M = Mptr ? Mptr[e] : Mconst;
    int m0 = blockIdx.y * 128;
    if (m0 >= M) return;
    int n0 = blockIdx.x * 128;

    const float* Wd  = Wd_base  + (size_t)e * Ddim * Hdim;
    const float* act = ACT_base + (size_t)e * Ntok * Hdim;
    const int* rowidx = rowidx_base ? rowidx_base + e * Ntok : nullptr;

    extern __shared__ float sm[];

    int tid = threadIdx.x, lane = tid & 31, wid = tid >> 5;
    int g = lane >> 2, tig = lane & 3;
    int wm = wid >> 2, wn = wid & 3;
    int mw = wm * 64, nw = wn * 32;

    int lr = tid >> 3, lc = tid & 7;
    const float* aptr[4];
    const float* bptr[4];
    #pragma unroll
    for (int i = 0; i < 4; i++) {
        int mm = m0 + lr + 32 * i;
        int src = mm < M ? mm : (M - 1);
        aptr[i] = act + (size_t)src * Hdim + lc * 4;      // ACT rows dense in list order
        bptr[i] = Wd  + (size_t)(n0 + lr + 32 * i) * Hdim + lc * 4;
    }
    int sO[4];
    #pragma unroll
    for (int i = 0; i < 4; i++) sO[i] = (lr + 32 * i) * 36 + lc * 4;

    int aBase[4], bBase[4];
    #pragma unroll
    for (int mf = 0; mf < 4; mf++) aBase[mf] = (mw + mf * 16 + g) * 36 + tig;
    #pragma unroll
    for (int nf = 0; nf < 4; nf++) bBase[nf] = (nw + nf * 8 + g) * 36 + tig;

    float acc[4][4][4];
    #pragma unroll
    for (int a = 0; a < 4; a++)
        #pragma unroll
        for (int b = 0; b < 4; b++)
            #pragma unroll
            for (int c = 0; c < 4; c++) acc[a][b][c] = 0.f;

    float4 pa[4], pb[4];
    #pragma unroll
    for (int i = 0; i < 4; i++) { pa[i] = *reinterpret_cast<const float4*>(aptr[i]);
                                  pb[i] = *reinterpret_cast<const float4*>(bptr[i]); }
    {
        float* D = sm;
        #pragma unroll
        for (int i = 0; i < 4; i++) { st4(D + sO[i], pa[i]); st4(D + 4608 + sO[i], pb[i]); }
    }
    __syncthreads();

    const int NT = Hdim / 32;
    for (int kt = 0; kt < NT; kt++) {
        int cur = kt & 1;
        if (kt + 1 < NT) {
            int off = (kt + 1) * 32;
            #pragma unroll
            for (int i = 0; i < 4; i++) { pa[i] = *reinterpret_cast<const float4*>(aptr[i] + off);
                                          pb[i] = *reinterpret_cast<const float4*>(bptr[i] + off); }
        }
        const uint32_t* A = reinterpret_cast<const uint32_t*>(sm + cur * STG2);
        const uint32_t* B = A + 4608;
        #pragma unroll
        for (int s = 0; s < 4; s++) {
            int k8 = s * 8;
            uint32_t af[4][4];
            #pragma unroll
            for (int mf = 0; mf < 4; mf++) {
                int rb = aBase[mf] + k8;
                af[mf][0] = A[rb];           af[mf][1] = A[rb + 8 * 36];
                af[mf][2] = A[rb + 4];       af[mf][3] = A[rb + 8 * 36 + 4];
            }
            uint32_t bf[4][2];
            #pragma unroll
            for (int nf = 0; nf < 4; nf++) {
                int rb = bBase[nf] + k8;
                bf[nf][0] = B[rb]; bf[nf][1] = B[rb + 4];
            }
            #pragma unroll
            for (int mf = 0; mf < 4; mf++)
                #pragma unroll
                for (int nf = 0; nf < 4; nf++)
                    mma_tf32(acc[mf][nf], af[mf][0], af[mf][1], af[mf][2], af[mf][3], bf[nf][0], bf[nf][1]);
        }
        if (kt + 1 < NT) {
            float* D = sm + (cur ^ 1) * STG2;
            #pragma unroll
            for (int i = 0; i < 4; i++) { st4(D + sO[i], pa[i]); st4(D + 4608 + sO[i], pb[i]); }
        }
        __syncthreads();
    }

    // epilogue
    #pragma unroll
    for (int mf = 0; mf < 4; mf++) {
        int m1 = m0 + mw + mf * 16 + g;
        int m2 = m1 + 8;
        #pragma unroll
        for (int nf = 0; nf < 4; nf++) {
            int n = n0 + nw + nf * 8 + 2 * tig;
            if (rowidx) {
                if (m1 < M) {
                    float* p = OUT + (size_t)rowidx[m1] * Ddim + n;
                    atomicAdd(p,     acc[mf][nf][0]);
                    atomicAdd(p + 1, acc[mf][nf][1]);
                }
                if (m2 < M) {
                    float* p = OUT + (size_t)rowidx[m2] * Ddim + n;
                    atomicAdd(p,     acc[mf][nf][2]);
                    atomicAdd(p + 1, acc[mf][nf][3]);
                }
            } else {
                if (m1 < M) {
                    float2 o; o.x = acc[mf][nf][0]; o.y = acc[mf][nf][1];
                    *reinterpret_cast<float2*>(OUT + (size_t)m1 * Ddim + n) = o;
                }
                if (m2 < M) {
                    float2 o; o.x = acc[mf][nf][2]; o.y = acc[mf][nf][3];
                    *reinterpret_cast<float2*>(OUT + (size_t)m2 * Ddim + n) = o;
                }
            }
        }
    }
}

// ---------------- launch ----------------
#define FFN1_SMEM (2 * STG1 * 4)
#define FFN2_SMEM (2 * STG2 * 4)

extern "C" void kernel_launch(void* const* d_in, const int* in_sizes, int n_in,
                              void* d_out, int out_size)
{
    const float* x   = (const float*)d_in[0];
    const float* rw  = (const float*)d_in[1];
    const float* rb  = (const float*)d_in[2];
    const float* gw  = (const float*)d_in[3];
    const float* uw  = (const float*)d_in[4];
    const float* dw  = (const float*)d_in[5];
    const float* shg = (const float*)d_in[6];
    const float* shu = (const float*)d_in[7];
    const float* shd = (const float*)d_in[8];
    float* out = (float*)d_out;

    float *act_r, *act_s, *wlist;
    int *list, *cnt;
    cudaGetSymbolAddress((void**)&act_r, g_act_r);
    cudaGetSymbolAddress((void**)&act_s, g_act_s);
    cudaGetSymbolAddress((void**)&list,  g_list);
    cudaGetSymbolAddress((void**)&wlist, g_wlist);
    cudaGetSymbolAddress((void**)&cnt,   g_count);

    cudaFuncSetAttribute(ffn1_mma, cudaFuncAttributeMaxDynamicSharedMemorySize, FFN1_SMEM);
    cudaFuncSetAttribute(ffn2_mma, cudaFuncAttributeMaxDynamicSharedMemorySize, FFN2_SMEM);

    init_kernel<<<1, 32>>>();
    router_kernel<<<Ntok, 256>>>(x, rw, rb);
    finalize_kernel<<<1, 1>>>(out, out_size);

    // gate/up + SwiGLU (+wt folded for routed)
    ffn1_mma<<<dim3(Hdim/64, Ntok/128, 1),    256, FFN1_SMEM>>>(x, shg, shu, act_s, nullptr, nullptr, nullptr, Ntok);
    ffn1_mma<<<dim3(Hdim/64, Ntok/128, Eexp), 256, FFN1_SMEM>>>(x, gw, uw, act_r, list, wlist, cnt, 0);

    // down-proj: shared writes every element, routed accumulates on top
    ffn2_mma<<<dim3(Ddim/128, Ntok/128, 1),    256, FFN2_SMEM>>>(act_s, shd, out, nullptr, nullptr, Ntok);
    ffn2_mma<<<dim3(Ddim/128, Ntok/128, Eexp), 256, FFN2_SMEM>>>(act_r, dw, out, list, cnt, 0);
}

// round 5
// speedup vs baseline: 4.0540x; 1.0909x over previous
#include <cuda_runtime.h>
#include <cstdint>

// Problem constants (B=2, S=1024, D=1024, E=8, K=2, H=2048)
#define Ntok 2048
#define Ddim 1024
#define Eexp 8
#define Hdim 2048
#define BSD  (2*1024*1024)
#define ZCOEF 1e-4f

// ---------------- scratch (static device globals) ----------------
__device__ float g_zsum;
__device__ float g_psum[Eexp];
__device__ int   g_count[Eexp];
__device__ int   g_list[Eexp * Ntok];
__device__ float g_wlist[Eexp * Ntok];
__device__ float g_act_r[(size_t)Eexp * Ntok * Hdim];  // routed SwiGLU activations (wt pre-folded)
__device__ float g_act_s[(size_t)Ntok * Hdim];         // shared-expert activations

// ---------------- helpers ----------------
__device__ __forceinline__ float rtf(float x) {
    uint32_t r;
    asm("cvt.rna.tf32.f32 %0, %1;" : "=r"(r) : "f"(x));
    return __uint_as_float(r);
}
__device__ __forceinline__ void mma_tf32(float c[4],
    const uint32_t a[4], uint32_t b0, uint32_t b1)
{
    asm volatile(
        "mma.sync.aligned.m16n8k8.row.col.f32.tf32.tf32.f32 "
        "{%0,%1,%2,%3}, {%4,%5,%6,%7}, {%8,%9}, {%0,%1,%2,%3};"
        : "+f"(c[0]), "+f"(c[1]), "+f"(c[2]), "+f"(c[3])
        : "r"(a[0]), "r"(a[1]), "r"(a[2]), "r"(a[3]), "r"(b0), "r"(b1));
}
__device__ __forceinline__ void ldsm4(uint32_t r[4], uint32_t addr) {
    asm volatile("ldmatrix.sync.aligned.m8n8.x4.shared.b16 {%0,%1,%2,%3}, [%4];"
        : "=r"(r[0]), "=r"(r[1]), "=r"(r[2]), "=r"(r[3]) : "r"(addr));
}
__device__ __forceinline__ uint32_t smem_u32(const void* p) {
    uint32_t a;
    asm("{ .reg .u64 t; cvta.to.shared.u64 t, %1; cvt.u32.u64 %0, t; }" : "=r"(a) : "l"(p));
    return a;
}
__device__ __forceinline__ float silu(float x) { return x / (1.f + __expf(-x)); }
__device__ __forceinline__ void st4(float* p, float4 v) {
    float4 t; t.x = rtf(v.x); t.y = rtf(v.y); t.z = rtf(v.z); t.w = rtf(v.w);
    *reinterpret_cast<float4*>(p) = t;
}

// ---------------- init ----------------
__global__ void init_kernel() {
    int t = threadIdx.x;
    if (t == 0) g_zsum = 0.f;
    if (t < Eexp) { g_psum[t] = 0.f; g_count[t] = 0; }
}

// ---------------- router ----------------
__global__ __launch_bounds__(256) void router_kernel(
    const float* __restrict__ x,
    const float* __restrict__ rw,
    const float* __restrict__ rb)
{
    int n = blockIdx.x;
    int t = threadIdx.x;
    int w = t >> 5, lane = t & 31;

    const float* xr = x + (size_t)n * Ddim;
    const float* wr = rw + (size_t)w * Ddim;
    float s = 0.f;
    for (int i = lane; i < Ddim; i += 32) s += xr[i] * wr[i];
    #pragma unroll
    for (int o = 16; o; o >>= 1) s += __shfl_xor_sync(0xFFFFFFFFu, s, o);

    __shared__ float logits[Eexp];
    if (lane == 0) logits[w] = s;
    __syncthreads();

    if (t == 0) {
        float l[Eexp], bsd[Eexp];
        float mx = -1e30f;
        #pragma unroll
        for (int e = 0; e < Eexp; e++) {
            l[e] = logits[e];
            bsd[e] = l[e] + rb[e];
            mx = fmaxf(mx, l[e]);
        }
        int i0 = 0;
        #pragma unroll
        for (int e = 1; e < Eexp; e++) if (bsd[e] > bsd[i0]) i0 = e;
        int i1 = (i0 == 0) ? 1 : 0;
        #pragma unroll
        for (int e = 0; e < Eexp; e++) if (e != i0 && bsd[e] > bsd[i1]) i1 = e;

        float l0 = l[i0], l1 = l[i1];
        float m2 = fmaxf(l0, l1);
        float e0 = expf(l0 - m2), e1 = expf(l1 - m2);
        float inv = 1.f / (e0 + e1);
        float w0 = e0 * inv, w1 = e1 * inv;

        float se = 0.f;
        #pragma unroll
        for (int e = 0; e < Eexp; e++) se += expf(l[e] - mx);
        float z = mx + logf(se);
        atomicAdd(&g_zsum, z * z);

        #pragma unroll
        for (int e = 0; e < Eexp; e++) atomicAdd(&g_psum[e], expf(l[e] - z));

        int p0 = atomicAdd(&g_count[i0], 1);
        g_list[i0 * Ntok + p0]  = n;
        g_wlist[i0 * Ntok + p0] = w0;
        int p1 = atomicAdd(&g_count[i1], 1);
        g_list[i1 * Ntok + p1]  = n;
        g_wlist[i1 * Ntok + p1] = w1;
    }
}

// ---------------- scalar outputs ----------------
__global__ void finalize_kernel(float* __restrict__ out, int out_size) {
    if (out_size >= BSD + 3) {
        float lb = 0.f;
        #pragma unroll
        for (int e = 0; e < Eexp; e++)
            lb += (g_psum[e] / (float)Ntok) * ((float)g_count[e] / (float)Ntok);
        out[BSD + 0] = 0.f;
        out[BSD + 1] = g_zsum / (float)Ntok * ZCOEF;
        out[BSD + 2] = lb * (float)Eexp;
    }
}

// =====================================================================
// ffn1_mma: act[m, n0..n0+63] = wt * silu(X@Wg^T) * (X@Wu^T)
// Single launch: z = 0..7 routed experts (gathered), z = 8 shared expert.
// CTA tile 128(m) x 64(n), K-tile 32. 8 warps (4m x 2n), warp 32x32(x2).
// Fragments via ldmatrix.x4 (36-float row stride -> conflict-free).
// =====================================================================
#define STG1 9216   // floats per stage: A 128*36=4608, Bg 64*36=2304, Bu 2304
__global__ __launch_bounds__(256, 2) void ffn1_mma(
    const float* __restrict__ X,
    const float* __restrict__ gw,
    const float* __restrict__ uw,
    const float* __restrict__ shg,
    const float* __restrict__ shu,
    float* __restrict__ actR,
    float* __restrict__ actS)
{
    int e = blockIdx.z;
    bool is_sh = (e == Eexp);
    int M = is_sh ? Ntok : g_count[e];
    int m0 = blockIdx.y * 128;
    if (m0 >= M) return;
    int n0 = blockIdx.x * 64;

    const float* Wg = is_sh ? shg : gw + (size_t)e * Hdim * Ddim;
    const float* Wu = is_sh ? shu : uw + (size_t)e * Hdim * Ddim;
    float* act = is_sh ? actS : actR + (size_t)e * Ntok * Hdim;
    const int* rowidx = is_sh ? nullptr : g_list + e * Ntok;
    const float* wl   = is_sh ? nullptr : g_wlist + e * Ntok;

    extern __shared__ float sm[];
    uint32_t smbase = smem_u32(sm);

    int tid = threadIdx.x, lane = tid & 31, wid = tid >> 5;
    int g = lane >> 2, tig = lane & 3;
    int wm = wid & 3, wn = wid >> 2;
    int mw = wm * 32, nw = wn * 32;

    // loader mapping
    int lr = tid >> 3, lc = tid & 7;
    const float* aptr[4];
    #pragma unroll
    for (int i = 0; i < 4; i++) {
        int mm = m0 + lr + 32 * i;
        int src = mm < M ? mm : (M - 1);
        int row = rowidx ? rowidx[src] : src;
        aptr[i] = X + (size_t)row * Ddim + lc * 4;
    }
    const float *gptr[2], *uptr[2];
    #pragma unroll
    for (int i = 0; i < 2; i++) {
        int r = n0 + lr + 32 * i;
        gptr[i] = Wg + (size_t)r * Ddim + lc * 4;
        uptr[i] = Wu + (size_t)r * Ddim + lc * 4;
    }
    int sA[4], sB[2];
    #pragma unroll
    for (int i = 0; i < 4; i++) sA[i] = (lr + 32 * i) * 36 + lc * 4;
    #pragma unroll
    for (int i = 0; i < 2; i++) sB[i] = (lr + 32 * i) * 36 + lc * 4;

    // ldmatrix per-thread byte offsets within a stage
    uint32_t afoff[2];
    #pragma unroll
    for (int mf = 0; mf < 2; mf++)
        afoff[mf] = ((mw + mf * 16 + (lane & 15)) * 36 + ((lane >> 4) << 2)) * 4;
    uint32_t bgoff[2], buoff[2];
    {
        int nrow = nw + ((lane >> 4) << 3) + (lane & 7);
        int cadd = ((lane >> 3) & 1) << 2;
        #pragma unroll
        for (int p = 0; p < 2; p++) {
            bgoff[p] = (4608 + (nrow + p * 16) * 36 + cadd) * 4;
            buoff[p] = bgoff[p] + 2304 * 4;
        }
    }

    float accg[2][4][4], accu[2][4][4];
    #pragma unroll
    for (int a = 0; a < 2; a++)
        #pragma unroll
        for (int b = 0; b < 4; b++)
            #pragma unroll
            for (int c = 0; c < 4; c++) { accg[a][b][c] = 0.f; accu[a][b][c] = 0.f; }

    float4 pa[4], pg[2], pu[2];
    #pragma unroll
    for (int i = 0; i < 4; i++) pa[i] = *reinterpret_cast<const float4*>(aptr[i]);
    #pragma unroll
    for (int i = 0; i < 2; i++) { pg[i] = *reinterpret_cast<const float4*>(gptr[i]);
                                  pu[i] = *reinterpret_cast<const float4*>(uptr[i]); }
    {
        float* D = sm;
        #pragma unroll
        for (int i = 0; i < 4; i++) st4(D + sA[i], pa[i]);
        #pragma unroll
        for (int i = 0; i < 2; i++) { st4(D + 4608 + sB[i], pg[i]); st4(D + 6912 + sB[i], pu[i]); }
    }
    __syncthreads();

    const int NT = Ddim / 32;
    for (int kt = 0; kt < NT; kt++) {
        int cur = kt & 1;
        if (kt + 1 < NT) {
            int off = (kt + 1) * 32;
            #pragma unroll
            for (int i = 0; i < 4; i++) pa[i] = *reinterpret_cast<const float4*>(aptr[i] + off);
            #pragma unroll
            for (int i = 0; i < 2; i++) { pg[i] = *reinterpret_cast<const float4*>(gptr[i] + off);
                                          pu[i] = *reinterpret_cast<const float4*>(uptr[i] + off); }
        }
        uint32_t stb = smbase + (uint32_t)cur * (STG1 * 4);
        #pragma unroll
        for (int s = 0; s < 4; s++) {
            uint32_t koff = s * 32;   // 8 floats per k-step
            uint32_t af[2][4], bg[2][4], bu[2][4];
            ldsm4(af[0], stb + afoff[0] + koff);
            ldsm4(af[1], stb + afoff[1] + koff);
            ldsm4(bg[0], stb + bgoff[0] + koff);
            ldsm4(bg[1], stb + bgoff[1] + koff);
            ldsm4(bu[0], stb + buoff[0] + koff);
            ldsm4(bu[1], stb + buoff[1] + koff);
            #pragma unroll
            for (int mf = 0; mf < 2; mf++)
                #pragma unroll
                for (int p = 0; p < 2; p++) {
                    mma_tf32(accg[mf][2*p  ], af[mf], bg[p][0], bg[p][1]);
                    mma_tf32(accg[mf][2*p+1], af[mf], bg[p][2], bg[p][3]);
                    mma_tf32(accu[mf][2*p  ], af[mf], bu[p][0], bu[p][1]);
                    mma_tf32(accu[mf][2*p+1], af[mf], bu[p][2], bu[p][3]);
                }
        }
        if (kt + 1 < NT) {
            float* D = sm + (cur ^ 1) * STG1;
            #pragma unroll
            for (int i = 0; i < 4; i++) st4(D + sA[i], pa[i]);
            #pragma unroll
            for (int i = 0; i < 2; i++) { st4(D + 4608 + sB[i], pg[i]); st4(D + 6912 + sB[i], pu[i]); }
        }
        __syncthreads();
    }

    // epilogue: act row m gets wt * silu(g) * u
    #pragma unroll
    for (int mf = 0; mf < 2; mf++) {
        int m1 = m0 + mw + mf * 16 + g;
        int m2 = m1 + 8;
        float wt1 = (m1 < M) ? (wl ? wl[m1] : 1.f) : 0.f;
        float wt2 = (m2 < M) ? (wl ? wl[m2] : 1.f) : 0.f;
        #pragma unroll
        for (int nf = 0; nf < 4; nf++) {
            int n = n0 + nw + nf * 8 + 2 * tig;
            if (m1 < M) {
                float2 o;
                o.x = wt1 * silu(accg[mf][nf][0]) * accu[mf][nf][0];
                o.y = wt1 * silu(accg[mf][nf][1]) * accu[mf][nf][1];
                *reinterpret_cast<float2*>(act + (size_t)m1 * Hdim + n) = o;
            }
            if (m2 < M) {
                float2 o;
                o.x = wt2 * silu(accg[mf][nf][2]) * accu[mf][nf][2];
                o.y = wt2 * silu(accg[mf][nf][3]) * accu[mf][nf][3];
                *reinterpret_cast<float2*>(act + (size_t)m2 * Hdim + n) = o;
            }
        }
    }
}

// =====================================================================
// ffn2_mma: Y = ACT @ Wd^T ; shared: plain store; routed: atomicAdd
// CTA tile 128x128, K-tile 32. 8 warps (2m x 4n), warp 64x32.
// =====================================================================
#define STG2 9216   // floats per stage: A 128*36=4608, B 128*36=4608
__global__ __launch_bounds__(256, 2) void ffn2_mma(
    const float* __restrict__ ACT_base,
    const float* __restrict__ Wd_base,
    float* __restrict__ OUT,
    const int* __restrict__ rowidx_base,
    const int* __restrict__ Mptr, int Mconst)
{
    int e = blockIdx.z;
    int M = Mptr ? Mptr[e] : Mconst;
    int m0 = blockIdx.y * 128;
    if (m0 >= M) return;
    int n0 = blockIdx.x * 128;

    const float* Wd  = Wd_base  + (size_t)e * Ddim * Hdim;
    const float* act = ACT_base + (size_t)e * Ntok * Hdim;
    const int* rowidx = rowidx_base ? rowidx_base + e * Ntok : nullptr;

    extern __shared__ float sm[];
    uint32_t smbase = smem_u32(sm);

    int tid = threadIdx.x, lane = tid & 31, wid = tid >> 5;
    int g = lane >> 2, tig = lane & 3;
    int wm = wid >> 2, wn = wid & 3;
    int mw = wm * 64, nw = wn * 32;

    int lr = tid >> 3, lc = tid & 7;
    const float* aptr[4];
    const float* bptr[4];
    #pragma unroll
    for (int i = 0; i < 4; i++) {
        int mm = m0 + lr + 32 * i;
        int src = mm < M ? mm : (M - 1);
        aptr[i] = act + (size_t)src * Hdim + lc * 4;      // ACT rows dense in list order
        bptr[i] = Wd  + (size_t)(n0 + lr + 32 * i) * Hdim + lc * 4;
    }
    int sO[4];
    #pragma unroll
    for (int i = 0; i < 4; i++) sO[i] = (lr + 32 * i) * 36 + lc * 4;

    uint32_t afoff[4];
    #pragma unroll
    for (int mf = 0; mf < 4; mf++)
        afoff[mf] = ((mw + mf * 16 + (lane & 15)) * 36 + ((lane >> 4) << 2)) * 4;
    uint32_t bfoff[2];
    {
        int nrow = nw + ((lane >> 4) << 3) + (lane & 7);
        int cadd = ((lane >> 3) & 1) << 2;
        #pragma unroll
        for (int p = 0; p < 2; p++)
            bfoff[p] = (4608 + (nrow + p * 16) * 36 + cadd) * 4;
    }

    float acc[4][4][4];
    #pragma unroll
    for (int a = 0; a < 4; a++)
        #pragma unroll
        for (int b = 0; b < 4; b++)
            #pragma unroll
            for (int c = 0; c < 4; c++) acc[a][b][c] = 0.f;

    float4 pa[4], pb[4];
    #pragma unroll
    for (int i = 0; i < 4; i++) { pa[i] = *reinterpret_cast<const float4*>(aptr[i]);
                                  pb[i] = *reinterpret_cast<const float4*>(bptr[i]); }
    {
        float* D = sm;
        #pragma unroll
        for (int i = 0; i < 4; i++) { st4(D + sO[i], pa[i]); st4(D + 4608 + sO[i], pb[i]); }
    }
    __syncthreads();

    const int NT = Hdim / 32;
    for (int kt = 0; kt < NT; kt++) {
        int cur = kt & 1;
        if (kt + 1 < NT) {
            int off = (kt + 1) * 32;
            #pragma unroll
            for (int i = 0; i < 4; i++) { pa[i] = *reinterpret_cast<const float4*>(aptr[i] + off);
                                          pb[i] = *reinterpret_cast<const float4*>(bptr[i] + off); }
        }
        uint32_t stb = smbase + (uint32_t)cur * (STG2 * 4);
        #pragma unroll
        for (int s = 0; s < 4; s++) {
            uint32_t koff = s * 32;
            uint32_t af[4][4], bf[2][4];
            ldsm4(af[0], stb + afoff[0] + koff);
            ldsm4(af[1], stb + afoff[1] + koff);
            ldsm4(af[2], stb + afoff[2] + koff);
            ldsm4(af[3], stb + afoff[3] + koff);
            ldsm4(bf[0], stb + bfoff[0] + koff);
            ldsm4(bf[1], stb + bfoff[1] + koff);
            #pragma unroll
            for (int mf = 0; mf < 4; mf++)
                #pragma unroll
                for (int p = 0; p < 2; p++) {
                    mma_tf32(acc[mf][2*p  ], af[mf], bf[p][0], bf[p][1]);
                    mma_tf32(acc[mf][2*p+1], af[mf], bf[p][2], bf[p][3]);
                }
        }
        if (kt + 1 < NT) {
            float* D = sm + (cur ^ 1) * STG2;
            #pragma unroll
            for (int i = 0; i < 4; i++) { st4(D + sO[i], pa[i]); st4(D + 4608 + sO[i], pb[i]); }
        }
        __syncthreads();
    }

    // epilogue
    #pragma unroll
    for (int mf = 0; mf < 4; mf++) {
        int m1 = m0 + mw + mf * 16 + g;
        int m2 = m1 + 8;
        #pragma unroll
        for (int nf = 0; nf < 4; nf++) {
            int n = n0 + nw + nf * 8 + 2 * tig;
            if (rowidx) {
                if (m1 < M) {
                    float* p = OUT + (size_t)rowidx[m1] * Ddim + n;
                    atomicAdd(p,     acc[mf][nf][0]);
                    atomicAdd(p + 1, acc[mf][nf][1]);
                }
                if (m2 < M) {
                    float* p = OUT + (size_t)rowidx[m2] * Ddim + n;
                    atomicAdd(p,     acc[mf][nf][2]);
                    atomicAdd(p + 1, acc[mf][nf][3]);
                }
            } else {
                if (m1 < M) {
                    float2 o; o.x = acc[mf][nf][0]; o.y = acc[mf][nf][1];
                    *reinterpret_cast<float2*>(OUT + (size_t)m1 * Ddim + n) = o;
                }
                if (m2 < M) {
                    float2 o; o.x = acc[mf][nf][2]; o.y = acc[mf][nf][3];
                    *reinterpret_cast<float2*>(OUT + (size_t)m2 * Ddim + n) = o;
                }
            }
        }
    }
}

// ---------------- launch ----------------
#define FFN1_SMEM (2 * STG1 * 4)
#define FFN2_SMEM (2 * STG2 * 4)

extern "C" void kernel_launch(void* const* d_in, const int* in_sizes, int n_in,
                              void* d_out, int out_size)
{
    const float* x   = (const float*)d_in[0];
    const float* rw  = (const float*)d_in[1];
    const float* rb  = (const float*)d_in[2];
    const float* gw  = (const float*)d_in[3];
    const float* uw  = (const float*)d_in[4];
    const float* dw  = (const float*)d_in[5];
    const float* shg = (const float*)d_in[6];
    const float* shu = (const float*)d_in[7];
    const float* shd = (const float*)d_in[8];
    float* out = (float*)d_out;

    float *act_r, *act_s;
    int *list, *cnt;
    cudaGetSymbolAddress((void**)&act_r, g_act_r);
    cudaGetSymbolAddress((void**)&act_s, g_act_s);
    cudaGetSymbolAddress((void**)&list,  g_list);
    cudaGetSymbolAddress((void**)&cnt,   g_count);

    cudaFuncSetAttribute(ffn1_mma, cudaFuncAttributeMaxDynamicSharedMemorySize, FFN1_SMEM);
    cudaFuncSetAttribute(ffn2_mma, cudaFuncAttributeMaxDynamicSharedMemorySize, FFN2_SMEM);

    init_kernel<<<1, 32>>>();
    router_kernel<<<Ntok, 256>>>(x, rw, rb);
    finalize_kernel<<<1, 1>>>(out, out_size);

    // gate/up + SwiGLU: z 0..7 routed (wt folded), z 8 shared — one launch
    ffn1_mma<<<dim3(Hdim/64, Ntok/128, Eexp + 1), 256, FFN1_SMEM>>>(
        x, gw, uw, shg, shu, act_r, act_s);

    // down-proj: shared writes every element, routed accumulates on top
    ffn2_mma<<<dim3(Ddim/128, Ntok/128, 1),    256, FFN2_SMEM>>>(act_s, shd, out, nullptr, nullptr, Ntok);
    ffn2_mma<<<dim3(Ddim/128, Ntok/128, Eexp), 256, FFN2_SMEM>>>(act_r, dw, out, list, cnt, 0);
}

// round 6
// speedup vs baseline: 4.2400x; 1.0459x over previous
#include <cuda_runtime.h>
#include <cstdint>

// Problem constants (B=2, S=1024, D=1024, E=8, K=2, H=2048)
#define Ntok 2048
#define Ddim 1024
#define Eexp 8
#define Hdim 2048
#define BSD  (2*1024*1024)
#define ZCOEF 1e-4f

// ---------------- scratch (static device globals) ----------------
__device__ float g_zsum;
__device__ float g_psum[Eexp];
__device__ int   g_count[Eexp];
__device__ int   g_list[Eexp * Ntok];
__device__ float g_wlist[Eexp * Ntok];
__device__ float g_act_r[(size_t)Eexp * Ntok * Hdim];   // routed SwiGLU act (wt folded, tf32-rounded)
__device__ float g_act_s[(size_t)Ntok * Hdim];          // shared-expert act (tf32-rounded)
// pre-rounded (tf32) copies
__device__ float g_gw_r[(size_t)Eexp * Hdim * Ddim];
__device__ float g_uw_r[(size_t)Eexp * Hdim * Ddim];
__device__ float g_dw_r[(size_t)Eexp * Ddim * Hdim];
__device__ float g_shg_r[(size_t)Hdim * Ddim];
__device__ float g_shu_r[(size_t)Hdim * Ddim];
__device__ float g_shd_r[(size_t)Ddim * Hdim];
__device__ float g_x_r[(size_t)Ntok * Ddim];

// ---------------- helpers ----------------
__device__ __forceinline__ float rtf(float x) {
    uint32_t r;
    asm("cvt.rna.tf32.f32 %0, %1;" : "=r"(r) : "f"(x));
    return __uint_as_float(r);
}
__device__ __forceinline__ void mma_tf32(float c[4],
    const uint32_t a[4], uint32_t b0, uint32_t b1)
{
    asm volatile(
        "mma.sync.aligned.m16n8k8.row.col.f32.tf32.tf32.f32 "
        "{%0,%1,%2,%3}, {%4,%5,%6,%7}, {%8,%9}, {%0,%1,%2,%3};"
        : "+f"(c[0]), "+f"(c[1]), "+f"(c[2]), "+f"(c[3])
        : "r"(a[0]), "r"(a[1]), "r"(a[2]), "r"(a[3]), "r"(b0), "r"(b1));
}
__device__ __forceinline__ void ldsm4(uint32_t r[4], uint32_t addr) {
    asm volatile("ldmatrix.sync.aligned.m8n8.x4.shared.b16 {%0,%1,%2,%3}, [%4];"
        : "=r"(r[0]), "=r"(r[1]), "=r"(r[2]), "=r"(r[3]) : "r"(addr));
}
__device__ __forceinline__ uint32_t smem_u32(const void* p) {
    uint32_t a;
    asm("{ .reg .u64 t; cvta.to.shared.u64 t, %1; cvt.u32.u64 %0, t; }" : "=r"(a) : "l"(p));
    return a;
}
__device__ __forceinline__ void cpa16(uint32_t dst, const float* src) {
    asm volatile("cp.async.ca.shared.global [%0], [%1], 16;" :: "r"(dst), "l"(src));
}
#define CP_COMMIT() asm volatile("cp.async.commit_group;" ::: "memory")
#define CP_WAIT1()  asm volatile("cp.async.wait_group 1;" ::: "memory")
#define CP_WAIT0()  asm volatile("cp.async.wait_group 0;" ::: "memory")
__device__ __forceinline__ float silu(float x) { return x / (1.f + __expf(-x)); }

// ---------------- init ----------------
__global__ void init_kernel() {
    int t = threadIdx.x;
    if (t == 0) g_zsum = 0.f;
    if (t < Eexp) { g_psum[t] = 0.f; g_count[t] = 0; }
}

// ---------------- tf32 pre-round kernels ----------------
__global__ __launch_bounds__(256) void round3_kernel(
    const float4* __restrict__ a, const float4* __restrict__ b, const float4* __restrict__ c,
    float4* __restrict__ oa, float4* __restrict__ ob, float4* __restrict__ oc, int n4)
{
    int i = blockIdx.x * 256 + threadIdx.x;
    if (i >= n4) return;
    const float4* s; float4* d;
    if (blockIdx.y == 0)      { s = a; d = oa; }
    else if (blockIdx.y == 1) { s = b; d = ob; }
    else                      { s = c; d = oc; }
    float4 v = s[i];
    float4 o; o.x = rtf(v.x); o.y = rtf(v.y); o.z = rtf(v.z); o.w = rtf(v.w);
    d[i] = o;
}
__global__ __launch_bounds__(256) void round4_kernel(
    const float4* __restrict__ a, const float4* __restrict__ b,
    const float4* __restrict__ c, const float4* __restrict__ e,
    float4* __restrict__ oa, float4* __restrict__ ob,
    float4* __restrict__ oc, float4* __restrict__ oe, int n4)
{
    int i = blockIdx.x * 256 + threadIdx.x;
    if (i >= n4) return;
    const float4* s; float4* d;
    if (blockIdx.y == 0)      { s = a; d = oa; }
    else if (blockIdx.y == 1) { s = b; d = ob; }
    else if (blockIdx.y == 2) { s = c; d = oc; }
    else                      { s = e; d = oe; }
    float4 v = s[i];
    float4 o; o.x = rtf(v.x); o.y = rtf(v.y); o.z = rtf(v.z); o.w = rtf(v.w);
    d[i] = o;
}

// ---------------- router (uses full-precision x) ----------------
__global__ __launch_bounds__(256) void router_kernel(
    const float* __restrict__ x,
    const float* __restrict__ rw,
    const float* __restrict__ rb)
{
    int n = blockIdx.x;
    int t = threadIdx.x;
    int w = t >> 5, lane = t & 31;

    const float* xr = x + (size_t)n * Ddim;
    const float* wr = rw + (size_t)w * Ddim;
    float s = 0.f;
    for (int i = lane; i < Ddim; i += 32) s += xr[i] * wr[i];
    #pragma unroll
    for (int o = 16; o; o >>= 1) s += __shfl_xor_sync(0xFFFFFFFFu, s, o);

    __shared__ float logits[Eexp];
    if (lane == 0) logits[w] = s;
    __syncthreads();

    if (t == 0) {
        float l[Eexp], bsd[Eexp];
        float mx = -1e30f;
        #pragma unroll
        for (int e = 0; e < Eexp; e++) {
            l[e] = logits[e];
            bsd[e] = l[e] + rb[e];
            mx = fmaxf(mx, l[e]);
        }
        int i0 = 0;
        #pragma unroll
        for (int e = 1; e < Eexp; e++) if (bsd[e] > bsd[i0]) i0 = e;
        int i1 = (i0 == 0) ? 1 : 0;
        #pragma unroll
        for (int e = 0; e < Eexp; e++) if (e != i0 && bsd[e] > bsd[i1]) i1 = e;

        float l0 = l[i0], l1 = l[i1];
        float m2 = fmaxf(l0, l1);
        float e0 = expf(l0 - m2), e1 = expf(l1 - m2);
        float inv = 1.f / (e0 + e1);
        float w0 = e0 * inv, w1 = e1 * inv;

        float se = 0.f;
        #pragma unroll
        for (int e = 0; e < Eexp; e++) se += expf(l[e] - mx);
        float z = mx + logf(se);
        atomicAdd(&g_zsum, z * z);

        #pragma unroll
        for (int e = 0; e < Eexp; e++) atomicAdd(&g_psum[e], expf(l[e] - z));

        int p0 = atomicAdd(&g_count[i0], 1);
        g_list[i0 * Ntok + p0]  = n;
        g_wlist[i0 * Ntok + p0] = w0;
        int p1 = atomicAdd(&g_count[i1], 1);
        g_list[i1 * Ntok + p1]  = n;
        g_wlist[i1 * Ntok + p1] = w1;
    }
}

// ---------------- scalar outputs ----------------
__global__ void finalize_kernel(float* __restrict__ out, int out_size) {
    if (out_size >= BSD + 3) {
        float lb = 0.f;
        #pragma unroll
        for (int e = 0; e < Eexp; e++)
            lb += (g_psum[e] / (float)Ntok) * ((float)g_count[e] / (float)Ntok);
        out[BSD + 0] = 0.f;
        out[BSD + 1] = g_zsum / (float)Ntok * ZCOEF;
        out[BSD + 2] = lb * (float)Eexp;
    }
}

// =====================================================================
// ffn1_mma: act[m, n0..n0+63] = rtf(wt * silu(X@Wg^T) * (X@Wu^T))
// Inputs pre-rounded to tf32; stages filled via cp.async (no CVT/STS).
// z = 0..7 routed experts (gathered), z = 8 shared expert.
// CTA tile 128(m) x 64(n), K-tile 32. 8 warps (4m x 2n).
// =====================================================================
#define STG1 9216   // floats per stage: A 128*36=4608, Bg 64*36=2304, Bu 2304
__global__ __launch_bounds__(256, 2) void ffn1_mma(
    const float* __restrict__ Xr,
    const float* __restrict__ gwr,
    const float* __restrict__ uwr,
    const float* __restrict__ shgr,
    const float* __restrict__ shur,
    float* __restrict__ actR,
    float* __restrict__ actS)
{
    int e = blockIdx.z;
    bool is_sh = (e == Eexp);
    int M = is_sh ? Ntok : g_count[e];
    int m0 = blockIdx.y * 128;
    if (m0 >= M) return;
    int n0 = blockIdx.x * 64;

    const float* Wg = is_sh ? shgr : gwr + (size_t)e * Hdim * Ddim;
    const float* Wu = is_sh ? shur : uwr + (size_t)e * Hdim * Ddim;
    float* act = is_sh ? actS : actR + (size_t)e * Ntok * Hdim;
    const int* rowidx = is_sh ? nullptr : g_list + e * Ntok;
    const float* wl   = is_sh ? nullptr : g_wlist + e * Ntok;

    extern __shared__ float sm[];
    uint32_t smbase = smem_u32(sm);

    int tid = threadIdx.x, lane = tid & 31, wid = tid >> 5;
    int g = lane >> 2, tig = lane & 3;
    int wm = wid & 3, wn = wid >> 2;
    int mw = wm * 32, nw = wn * 32;

    // loader mapping: thread -> rows (lr + 32i), 16B chunk lc
    int lr = tid >> 3, lc = tid & 7;
    const float* aptr[4];
    #pragma unroll
    for (int i = 0; i < 4; i++) {
        int mm = m0 + lr + 32 * i;
        int src = mm < M ? mm : (M - 1);
        int row = rowidx ? rowidx[src] : src;
        aptr[i] = Xr + (size_t)row * Ddim + lc * 4;
    }
    const float *gptr[2], *uptr[2];
    #pragma unroll
    for (int i = 0; i < 2; i++) {
        int r = n0 + lr + 32 * i;
        gptr[i] = Wg + (size_t)r * Ddim + lc * 4;
        uptr[i] = Wu + (size_t)r * Ddim + lc * 4;
    }
    // smem byte offsets for this thread's 8 chunks
    uint32_t dA[4], dG[2], dU[2];
    #pragma unroll
    for (int i = 0; i < 4; i++) dA[i] = ((lr + 32 * i) * 36 + lc * 4) * 4;
    #pragma unroll
    for (int i = 0; i < 2; i++) {
        dG[i] = (4608 + (lr + 32 * i) * 36 + lc * 4) * 4;
        dU[i] = dG[i] + 2304 * 4;
    }

    // ldmatrix per-thread byte offsets within a stage
    uint32_t afoff[2];
    #pragma unroll
    for (int mf = 0; mf < 2; mf++)
        afoff[mf] = ((mw + mf * 16 + (lane & 15)) * 36 + ((lane >> 4) << 2)) * 4;
    uint32_t bgoff[2], buoff[2];
    {
        int nrow = nw + ((lane >> 4) << 3) + (lane & 7);
        int cadd = ((lane >> 3) & 1) << 2;
        #pragma unroll
        for (int p = 0; p < 2; p++) {
            bgoff[p] = (4608 + (nrow + p * 16) * 36 + cadd) * 4;
            buoff[p] = bgoff[p] + 2304 * 4;
        }
    }

    float accg[2][4][4], accu[2][4][4];
    #pragma unroll
    for (int a = 0; a < 2; a++)
        #pragma unroll
        for (int b = 0; b < 4; b++)
            #pragma unroll
            for (int c = 0; c < 4; c++) { accg[a][b][c] = 0.f; accu[a][b][c] = 0.f; }

    // stage 0 fill
    {
        uint32_t sb = smbase;
        #pragma unroll
        for (int i = 0; i < 4; i++) cpa16(sb + dA[i], aptr[i]);
        #pragma unroll
        for (int i = 0; i < 2; i++) { cpa16(sb + dG[i], gptr[i]); cpa16(sb + dU[i], uptr[i]); }
        CP_COMMIT();
    }

    const int NT = Ddim / 32;
    for (int kt = 0; kt < NT; kt++) {
        int cur = kt & 1;
        if (kt + 1 < NT) {
            uint32_t sb = smbase + (uint32_t)(cur ^ 1) * (STG1 * 4);
            int off = (kt + 1) * 32;
            #pragma unroll
            for (int i = 0; i < 4; i++) cpa16(sb + dA[i], aptr[i] + off);
            #pragma unroll
            for (int i = 0; i < 2; i++) { cpa16(sb + dG[i], gptr[i] + off); cpa16(sb + dU[i], uptr[i] + off); }
            CP_COMMIT();
            CP_WAIT1();
        } else {
            CP_WAIT0();
        }
        __syncthreads();

        uint32_t stb = smbase + (uint32_t)cur * (STG1 * 4);
        #pragma unroll
        for (int s = 0; s < 4; s++) {
            uint32_t koff = s * 32;   // 8 floats per k-step
            uint32_t af[2][4], bg[2][4], bu[2][4];
            ldsm4(af[0], stb + afoff[0] + koff);
            ldsm4(af[1], stb + afoff[1] + koff);
            ldsm4(bg[0], stb + bgoff[0] + koff);
            ldsm4(bg[1], stb + bgoff[1] + koff);
            ldsm4(bu[0], stb + buoff[0] + koff);
            ldsm4(bu[1], stb + buoff[1] + koff);
            #pragma unroll
            for (int mf = 0; mf < 2; mf++)
                #pragma unroll
                for (int p = 0; p < 2; p++) {
                    mma_tf32(accg[mf][2*p  ], af[mf], bg[p][0], bg[p][1]);
                    mma_tf32(accg[mf][2*p+1], af[mf], bg[p][2], bg[p][3]);
                    mma_tf32(accu[mf][2*p  ], af[mf], bu[p][0], bu[p][1]);
                    mma_tf32(accu[mf][2*p+1], af[mf], bu[p][2], bu[p][3]);
                }
        }
        __syncthreads();
    }

    // epilogue: act row m gets rtf(wt * silu(g) * u)
    #pragma unroll
    for (int mf = 0; mf < 2; mf++) {
        int m1 = m0 + mw + mf * 16 + g;
        int m2 = m1 + 8;
        float wt1 = (m1 < M) ? (wl ? wl[m1] : 1.f) : 0.f;
        float wt2 = (m2 < M) ? (wl ? wl[m2] : 1.f) : 0.f;
        #pragma unroll
        for (int nf = 0; nf < 4; nf++) {
            int n = n0 + nw + nf * 8 + 2 * tig;
            if (m1 < M) {
                float2 o;
                o.x = rtf(wt1 * silu(accg[mf][nf][0]) * accu[mf][nf][0]);
                o.y = rtf(wt1 * silu(accg[mf][nf][1]) * accu[mf][nf][1]);
                *reinterpret_cast<float2*>(act + (size_t)m1 * Hdim + n) = o;
            }
            if (m2 < M) {
                float2 o;
                o.x = rtf(wt2 * silu(accg[mf][nf][2]) * accu[mf][nf][2]);
                o.y = rtf(wt2 * silu(accg[mf][nf][3]) * accu[mf][nf][3]);
                *reinterpret_cast<float2*>(act + (size_t)m2 * Hdim + n) = o;
            }
        }
    }
}

// =====================================================================
// ffn2_mma: Y = ACT @ Wd^T ; shared: plain store; routed: atomicAdd
// CTA tile 128x128, K-tile 32. 8 warps (2m x 4n). cp.async stage fills.
// =====================================================================
#define STG2 9216   // floats per stage: A 128*36=4608, B 128*36=4608
__global__ __launch_bounds__(256, 2) void ffn2_mma(
    const float* __restrict__ ACT_base,
    const float* __restrict__ Wd_base,
    float* __restrict__ OUT,
    const int* __restrict__ rowidx_base,
    const int* __restrict__ Mptr, int Mconst)
{
    int e = blockIdx.z;
    int M = Mptr ? Mptr[e] : Mconst;
    int m0 = blockIdx.y * 128;
    if (m0 >= M) return;
    int n0 = blockIdx.x * 128;

    const float* Wd  = Wd_base  + (size_t)e * Ddim * Hdim;
    const float* act = ACT_base + (size_t)e * Ntok * Hdim;
    const int* rowidx = rowidx_base ? rowidx_base + e * Ntok : nullptr;

    extern __shared__ float sm[];
    uint32_t smbase = smem_u32(sm);

    int tid = threadIdx.x, lane = tid & 31, wid = tid >> 5;
    int g = lane >> 2, tig = lane & 3;
    int wm = wid >> 2, wn = wid & 3;
    int mw = wm * 64, nw = wn * 32;

    int lr = tid >> 3, lc = tid & 7;
    const float* aptr[4];
    const float* bptr[4];
    #pragma unroll
    for (int i = 0; i < 4; i++) {
        int mm = m0 + lr + 32 * i;
        int src = mm < M ? mm : (M - 1);
        aptr[i] = act + (size_t)src * Hdim + lc * 4;      // ACT rows dense in list order
        bptr[i] = Wd  + (size_t)(n0 + lr + 32 * i) * Hdim + lc * 4;
    }
    uint32_t dA[4], dB[4];
    #pragma unroll
    for (int i = 0; i < 4; i++) {
        dA[i] = ((lr + 32 * i) * 36 + lc * 4) * 4;
        dB[i] = (4608 + (lr + 32 * i) * 36 + lc * 4) * 4;
    }

    uint32_t afoff[4];
    #pragma unroll
    for (int mf = 0; mf < 4; mf++)
        afoff[mf] = ((mw + mf * 16 + (lane & 15)) * 36 + ((lane >> 4) << 2)) * 4;
    uint32_t bfoff[2];
    {
        int nrow = nw + ((lane >> 4) << 3) + (lane & 7);
        int cadd = ((lane >> 3) & 1) << 2;
        #pragma unroll
        for (int p = 0; p < 2; p++)
            bfoff[p] = (4608 + (nrow + p * 16) * 36 + cadd) * 4;
    }

    float acc[4][4][4];
    #pragma unroll
    for (int a = 0; a < 4; a++)
        #pragma unroll
        for (int b = 0; b < 4; b++)
            #pragma unroll
            for (int c = 0; c < 4; c++) acc[a][b][c] = 0.f;

    // stage 0 fill
    {
        uint32_t sb = smbase;
        #pragma unroll
        for (int i = 0; i < 4; i++) { cpa16(sb + dA[i], aptr[i]); cpa16(sb + dB[i], bptr[i]); }
        CP_COMMIT();
    }

    const int NT = Hdim / 32;
    for (int kt = 0; kt < NT; kt++) {
        int cur = kt & 1;
        if (kt + 1 < NT) {
            uint32_t sb = smbase + (uint32_t)(cur ^ 1) * (STG2 * 4);
            int off = (kt + 1) * 32;
            #pragma unroll
            for (int i = 0; i < 4; i++) { cpa16(sb + dA[i], aptr[i] + off); cpa16(sb + dB[i], bptr[i] + off); }
            CP_COMMIT();
            CP_WAIT1();
        } else {
            CP_WAIT0();
        }
        __syncthreads();

        uint32_t stb = smbase + (uint32_t)cur * (STG2 * 4);
        #pragma unroll
        for (int s = 0; s < 4; s++) {
            uint32_t koff = s * 32;
            uint32_t af[4][4], bf[2][4];
            ldsm4(af[0], stb + afoff[0] + koff);
            ldsm4(af[1], stb + afoff[1] + koff);
            ldsm4(af[2], stb + afoff[2] + koff);
            ldsm4(af[3], stb + afoff[3] + koff);
            ldsm4(bf[0], stb + bfoff[0] + koff);
            ldsm4(bf[1], stb + bfoff[1] + koff);
            #pragma unroll
            for (int mf = 0; mf < 4; mf++)
                #pragma unroll
                for (int p = 0; p < 2; p++) {
                    mma_tf32(acc[mf][2*p  ], af[mf], bf[p][0], bf[p][1]);
                    mma_tf32(acc[mf][2*p+1], af[mf], bf[p][2], bf[p][3]);
                }
        }
        __syncthreads();
    }

    // epilogue
    #pragma unroll
    for (int mf = 0; mf < 4; mf++) {
        int m1 = m0 + mw + mf * 16 + g;
        int m2 = m1 + 8;
        #pragma unroll
        for (int nf = 0; nf < 4; nf++) {
            int n = n0 + nw + nf * 8 + 2 * tig;
            if (rowidx) {
                if (m1 < M) {
                    float* p = OUT + (size_t)rowidx[m1] * Ddim + n;
                    atomicAdd(p,     acc[mf][nf][0]);
                    atomicAdd(p + 1, acc[mf][nf][1]);
                }
                if (m2 < M) {
                    float* p = OUT + (size_t)rowidx[m2] * Ddim + n;
                    atomicAdd(p,     acc[mf][nf][2]);
                    atomicAdd(p + 1, acc[mf][nf][3]);
                }
            } else {
                if (m1 < M) {
                    float2 o; o.x = acc[mf][nf][0]; o.y = acc[mf][nf][1];
                    *reinterpret_cast<float2*>(OUT + (size_t)m1 * Ddim + n) = o;
                }
                if (m2 < M) {
                    float2 o; o.x = acc[mf][nf][2]; o.y = acc[mf][nf][3];
                    *reinterpret_cast<float2*>(OUT + (size_t)m2 * Ddim + n) = o;
                }
            }
        }
    }
}

// ---------------- launch ----------------
#define FFN1_SMEM (2 * STG1 * 4)
#define FFN2_SMEM (2 * STG2 * 4)

extern "C" void kernel_launch(void* const* d_in, const int* in_sizes, int n_in,
                              void* d_out, int out_size)
{
    const float* x   = (const float*)d_in[0];
    const float* rw  = (const float*)d_in[1];
    const float* rb  = (const float*)d_in[2];
    const float* gw  = (const float*)d_in[3];
    const float* uw  = (const float*)d_in[4];
    const float* dw  = (const float*)d_in[5];
    const float* shg = (const float*)d_in[6];
    const float* shu = (const float*)d_in[7];
    const float* shd = (const float*)d_in[8];
    float* out = (float*)d_out;

    float *act_r, *act_s, *gw_r, *uw_r, *dw_r, *shg_r, *shu_r, *shd_r, *x_r;
    int *list, *cnt;
    cudaGetSymbolAddress((void**)&act_r, g_act_r);
    cudaGetSymbolAddress((void**)&act_s, g_act_s);
    cudaGetSymbolAddress((void**)&gw_r,  g_gw_r);
    cudaGetSymbolAddress((void**)&uw_r,  g_uw_r);
    cudaGetSymbolAddress((void**)&dw_r,  g_dw_r);
    cudaGetSymbolAddress((void**)&shg_r, g_shg_r);
    cudaGetSymbolAddress((void**)&shu_r, g_shu_r);
    cudaGetSymbolAddress((void**)&shd_r, g_shd_r);
    cudaGetSymbolAddress((void**)&x_r,   g_x_r);
    cudaGetSymbolAddress((void**)&list,  g_list);
    cudaGetSymbolAddress((void**)&cnt,   g_count);

    cudaFuncSetAttribute(ffn1_mma, cudaFuncAttributeMaxDynamicSharedMemorySize, FFN1_SMEM);
    cudaFuncSetAttribute(ffn2_mma, cudaFuncAttributeMaxDynamicSharedMemorySize, FFN2_SMEM);

    init_kernel<<<1, 32>>>();

    // pre-round weights + x to tf32 (rna) once per call
    {
        int nBig = Eexp * Hdim * Ddim / 4;     // 4.19M float4 per tensor
        int nSm  = Hdim * Ddim / 4;            // 524K float4 per tensor
        round3_kernel<<<dim3((nBig + 255) / 256, 3), 256>>>(
            (const float4*)gw, (const float4*)uw, (const float4*)dw,
            (float4*)gw_r, (float4*)uw_r, (float4*)dw_r, nBig);
        round4_kernel<<<dim3((nSm + 255) / 256, 4), 256>>>(
            (const float4*)shg, (const float4*)shu, (const float4*)shd, (const float4*)x,
            (float4*)shg_r, (float4*)shu_r, (float4*)shd_r, (float4*)x_r, nSm);
    }

    router_kernel<<<Ntok, 256>>>(x, rw, rb);
    finalize_kernel<<<1, 1>>>(out, out_size);

    // gate/up + SwiGLU: z 0..7 routed (wt folded), z 8 shared — one launch
    ffn1_mma<<<dim3(Hdim/64, Ntok/128, Eexp + 1), 256, FFN1_SMEM>>>(
        x_r, gw_r, uw_r, shg_r, shu_r, act_r, act_s);

    // down-proj: shared writes every element, routed accumulates on top
    ffn2_mma<<<dim3(Ddim/128, Ntok/128, 1),    256, FFN2_SMEM>>>(act_s, shd_r, out, nullptr, nullptr, Ntok);
    ffn2_mma<<<dim3(Ddim/128, Ntok/128, Eexp), 256, FFN2_SMEM>>>(act_r, dw_r, out, list, cnt, 0);
}